// round 13
// baseline (speedup 1.0000x reference)
#include <cuda_runtime.h>
#include <math.h>
#include <stdint.h>

#define N_ROWS   524288
#define D_IN     64
#define H_DIM    128
#define D_Z      16
#define K_CODES  256
#define TILE_M   128
#define NTHREADS 512
#define NTILES   (N_ROWS / TILE_M)

#define CS   132      // CTs row stride (floats)
#define ASR  68       // ATs row stride
#define MARGIN 0.02f

// ---- smem layout (float offsets) ----
#define OFF_ATS  0            // 4352 ; alias W3S (4096) after G1
#define OFF_CTS  4352         // 16896 = 128 cols * 132
#define OFF_SWB  21248        // 16384 : A @ +0 (8192), B @ +8192
#define OFF_SWA  21248
#define OFF_SWBB 29440
// aliases into SWB region (dead after B3):
#define OFF_ZS   21248        // 2560
#define OFF_MLB  23808        // 4224 (128 rows * 33)
#define OFF_CN   28032        // 256
#define OFF_RED  28288        // 512
#define OFF_SEC  28800        // 512
#define OFF_REDI 29312        // 512
#define OFF_MWB0 37632        // 8192 (32KB)
#define OFF_MWB1 45824        // 8192 (32KB)
#define OFF_B1S  54016        // 128
#define OFF_B2S  54144        // 128
#define OFF_BML  54272        // 32
#define SMEM_FLOATS 54304
#define SMEM_BYTES  (SMEM_FLOATS * 4)   // 217216

typedef unsigned long long u64;

// mma weight images (hi/lo split, fragment-ordered)
__device__ __align__(16) float g_w1img[16384];   // 2 halves x 2048 float4
__device__ __align__(16) float g_w2img[32768];   // 4 quarters x 2048 float4
__device__ __align__(16) float g_w3img[8192];    // 2048 float4
__device__ float g_partial[NTILES];
__device__ int   g_fixcount;
__device__ float g_fixloss;
__device__ int   g_fixlist[N_ROWS];

// ---- helpers ----
__device__ __forceinline__ uint32_t smem_u32(const void* p) {
    uint32_t a;
    asm("{ .reg .u64 t; cvta.to.shared.u64 t, %1; cvt.u32.u64 %0, t; }" : "=r"(a) : "l"(p));
    return a;
}
__device__ __forceinline__ void split32(float v, uint32_t& h, uint32_t& l) {
    asm("cvt.rna.tf32.f32 %0, %1;" : "=r"(h) : "f"(v));
    float hf = __uint_as_float(h);
    asm("cvt.rna.tf32.f32 %0, %1;" : "=r"(l) : "f"(v - hf));
}
__device__ __forceinline__ void mma8(float* c, uint32_t a0, uint32_t a1, uint32_t a2, uint32_t a3,
                                     uint32_t b0, uint32_t b1) {
    asm volatile("mma.sync.aligned.m16n8k8.row.col.f32.tf32.tf32.f32 "
                 "{%0,%1,%2,%3},{%4,%5,%6,%7},{%8,%9},{%0,%1,%2,%3};"
                 : "+f"(c[0]), "+f"(c[1]), "+f"(c[2]), "+f"(c[3])
                 : "r"(a0), "r"(a1), "r"(a2), "r"(a3), "r"(b0), "r"(b1));
}
__device__ __forceinline__ void cp16(uint32_t dst, const void* src) {
    asm volatile("cp.async.cg.shared.global [%0], [%1], 16;" :: "r"(dst), "l"(src) : "memory");
}
#define CP_COMMIT() asm volatile("cp.async.commit_group;" ::: "memory")
#define CP_WAIT0()  asm volatile("cp.async.wait_group 0;" ::: "memory")

__device__ __forceinline__ u64 bcast2(float x) { u64 r; asm("mov.b64 %0, {%1, %1};" : "=l"(r) : "f"(x)); return r; }
__device__ __forceinline__ void unpack2(u64 v, float& x, float& y) { asm("mov.b64 {%0, %1}, %2;" : "=f"(x), "=f"(y) : "l"(v)); }
__device__ __forceinline__ void fma2(u64& d, u64 a, u64 b) { asm("fma.rn.f32x2 %0, %1, %2, %3;" : "=l"(d) : "l"(a), "l"(b), "l"(d)); }

// ---- setup: split weight images + reset fix state ----
__global__ void setup_kernel(const float* __restrict__ W1, const float* __restrict__ W2,
                             const float* __restrict__ Wmu, const float* __restrict__ Wlv)
{
    if (blockIdx.x == 0 && threadIdx.x == 0) { g_fixcount = 0; g_fixloss = 0.f; }
    int t = blockIdx.x * blockDim.x + threadIdx.x;
    int nt = gridDim.x * blockDim.x;
    // W1img: 2 halves (k 0-31, 32-63), each 2048 float4
    for (int e = t; e < 4096; e += nt) {
        int h = e >> 11, f = e & 2047;
        int sl = f >> 9, n8 = (f >> 5) & 15, L = f & 31;
        int k0 = h * 32 + sl * 8 + (L & 3), n = n8 * 8 + (L >> 2);
        uint32_t h0, l0, h1, l1;
        split32(W1[k0 * 128 + n], h0, l0);
        split32(W1[(k0 + 4) * 128 + n], h1, l1);
        ((float4*)g_w1img)[e] = make_float4(__uint_as_float(h0), __uint_as_float(h1),
                                            __uint_as_float(l0), __uint_as_float(l1));
    }
    // W2img: 4 quarters (k 0-31, 32-63, 64-95, 96-127)
    for (int e = t; e < 8192; e += nt) {
        int q = e >> 11, f = e & 2047;
        int sl = f >> 9, n8 = (f >> 5) & 15, L = f & 31;
        int k0 = q * 32 + sl * 8 + (L & 3), n = n8 * 8 + (L >> 2);
        uint32_t h0, l0, h1, l1;
        split32(W2[k0 * 128 + n], h0, l0);
        split32(W2[(k0 + 4) * 128 + n], h1, l1);
        ((float4*)g_w2img)[e] = make_float4(__uint_as_float(h0), __uint_as_float(h1),
                                            __uint_as_float(l0), __uint_as_float(l1));
    }
    // W3img: [Wmu|Wlv] 128k x 32n: 16 s x 4 n8
    for (int f = t; f < 2048; f += nt) {
        int s = f >> 7, n8 = (f >> 5) & 3, L = f & 31;
        int k0 = s * 8 + (L & 3), n = n8 * 8 + (L >> 2);
        float b0 = (n < 16) ? Wmu[k0 * 16 + n] : Wlv[k0 * 16 + n - 16];
        float b1 = (n < 16) ? Wmu[(k0 + 4) * 16 + n] : Wlv[(k0 + 4) * 16 + n - 16];
        uint32_t h0, l0, h1, l1;
        split32(b0, h0, l0); split32(b1, h1, l1);
        ((float4*)g_w3img)[f] = make_float4(__uint_as_float(h0), __uint_as_float(h1),
                                            __uint_as_float(l0), __uint_as_float(l1));
    }
}

// mma 3-term k-step, A from CTs (transposed [col][row])
__device__ __forceinline__ void mma_step3(float (*c)[4], const float* CTs, const uint4* img,
                                          int s_local, int kglob, int rowb, int n8base,
                                          int L, int NTIMG, int NT8)
{
    int k0 = kglob * 8 + (L & 3);
    int r  = rowb + (L >> 2);
    float a0v = CTs[k0 * CS + r];
    float a1v = CTs[k0 * CS + r + 8];
    float a2v = CTs[(k0 + 4) * CS + r];
    float a3v = CTs[(k0 + 4) * CS + r + 8];
    uint32_t ah0, al0, ah1, al1, ah2, al2, ah3, al3;
    split32(a0v, ah0, al0); split32(a1v, ah1, al1);
    split32(a2v, ah2, al2); split32(a3v, ah3, al3);
    #pragma unroll
    for (int i = 0; i < 8; ++i) {
        if (i >= NT8) break;
        uint4 B = img[(s_local * NTIMG + n8base + i) * 32 + L];
        mma8(c[i], ah0, ah1, ah2, ah3, B.x, B.y);
        mma8(c[i], ah0, ah1, ah2, ah3, B.z, B.w);
        mma8(c[i], al0, al1, al2, al3, B.x, B.y);
    }
}

// mma 3-term k-step, A from registers (GEMM1)
__device__ __forceinline__ void mma_g1step3(float (*c)[4], const float* aXs, const uint4* img,
                                            int s_local, int n8base, int L)
{
    uint32_t ah0, al0, ah1, al1, ah2, al2, ah3, al3;
    split32(aXs[0], ah0, al0); split32(aXs[1], ah1, al1);
    split32(aXs[2], ah2, al2); split32(aXs[3], ah3, al3);
    #pragma unroll
    for (int i = 0; i < 8; ++i) {
        uint4 B = img[(s_local * 16 + n8base + i) * 32 + L];
        mma8(c[i], ah0, ah1, ah2, ah3, B.x, B.y);
        mma8(c[i], ah0, ah1, ah2, ah3, B.z, B.w);
        mma8(c[i], al0, al1, al2, al3, B.x, B.y);
    }
}

__global__ __launch_bounds__(NTHREADS, 1)
void enc_kernel(const float* __restrict__ feats,
                const float* __restrict__ W1g,  const float* __restrict__ b1,
                const float* __restrict__ W2g,  const float* __restrict__ b2,
                const float* __restrict__ Wmu, const float* __restrict__ bmu,
                const float* __restrict__ Wlv, const float* __restrict__ blv,
                const float* __restrict__ codebook, const float* __restrict__ eps,
                float* __restrict__ outZ,  float* __restrict__ outMu,
                float* __restrict__ outLv, float* __restrict__ outZq)
{
    extern __shared__ float sm[];
    const uint32_t sb = smem_u32(sm);
    const int tid = threadIdx.x;
    const int w   = tid >> 5;
    const int L   = tid & 31;
    const int tile = blockIdx.x;
    const int row0 = tile * TILE_M;

    float* ATs  = sm + OFF_ATS;
    float* W3S  = sm + OFF_ATS;      // alias after G1
    float* CTs  = sm + OFF_CTS;
    float* SWA  = sm + OFF_SWA;
    float* SWBB = sm + OFF_SWBB;
    float* ZS   = sm + OFF_ZS;
    float* MLB  = sm + OFF_MLB;
    float* CNs  = sm + OFF_CN;
    float* REDs = sm + OFF_RED;
    float* SECs = sm + OFF_SEC;
    int*   REDi = (int*)(sm + OFF_REDI);
    float* B1s  = sm + OFF_B1S;
    float* B2s  = sm + OFF_B2S;
    float* BMLs = sm + OFF_BML;
    const uint4* MW0 = (const uint4*)(sm + OFF_MWB0);
    const uint4* MW1 = (const uint4*)(sm + OFF_MWB1);
    const float* CBs = sm + OFF_MWB1;   // codebook lands in MWB1 at the end

    const bool is_s = (w < 8);
    const int  mw   = w - 8;                       // mma warp id 0..7
    const int  rowb = 64 + ((mw >> 1) & 3) * 16;   // mma rows
    const int  n8b  = (mw & 1) * 8;                // mma col half

    // scalar mapping
    const int stx = tid & 31;
    const int sty = tid >> 5;        // 0..7 for scalar threads
    const int r0  = sty * 8;
    const int c0  = stx * 4;

    // ---- preload copies ----
    for (int i = tid; i < 2048; i += NTHREADS) cp16(sb + (OFF_SWA << 2) + i * 16, W1g + i * 4);
    for (int i = tid; i < 2048; i += NTHREADS) cp16(sb + (OFF_SWBB << 2) + i * 16, W2g + i * 4);
    for (int i = tid; i < 2048; i += NTHREADS) cp16(sb + (OFF_MWB0 << 2) + i * 16, g_w1img + i * 4);
    for (int i = tid; i < 2048; i += NTHREADS) cp16(sb + (OFF_MWB1 << 2) + i * 16, g_w1img + 8192 + i * 4);
    CP_COMMIT();

    // X transpose (rows 0..63) for scalar half
    {
        const float4* Xg = (const float4*)(feats + (size_t)row0 * D_IN);
        #pragma unroll
        for (int it = 0; it < 2; ++it) {
            int i = tid + it * NTHREADS;   // 0..1023
            float4 v = Xg[i];
            int r  = i >> 4;
            int k0 = (i & 15) << 2;
            ATs[(k0+0)*ASR + r] = v.x;
            ATs[(k0+1)*ASR + r] = v.y;
            ATs[(k0+2)*ASR + r] = v.z;
            ATs[(k0+3)*ASR + r] = v.w;
        }
    }
    // mma X fragments (rows 64..127) from gmem
    float aX[8][4];
    if (!is_s) {
        const float* fb = feats + (size_t)(row0 + rowb + (L >> 2)) * D_IN + (L & 3);
        #pragma unroll
        for (int s = 0; s < 8; ++s) {
            aX[s][0] = fb[s * 8];
            aX[s][1] = fb[512 + s * 8];
            aX[s][2] = fb[s * 8 + 4];
            aX[s][3] = fb[512 + s * 8 + 4];
        }
    }
    if (tid < 128) { B1s[tid] = b1[tid]; B2s[tid] = b2[tid]; }
    if (tid >= 128 && tid < 160) { int q = tid - 128; BMLs[q] = (q < 16) ? bmu[q] : blv[q - 16]; }

    CP_WAIT0();
    __syncthreads();   // B0

    // scalar accumulators
    u64 acc2[8][2];
    #pragma unroll
    for (int i = 0; i < 8; ++i) { acc2[i][0] = 0ULL; acc2[i][1] = 0ULL; }
    // mma accumulators
    float c[8][4];
    #pragma unroll
    for (int i = 0; i < 8; ++i) { c[i][0] = c[i][1] = c[i][2] = c[i][3] = 0.f; }

    // ================= GEMM1 part a (k 0..31) =================
    if (is_s) {
        #pragma unroll 4
        for (int k = 0; k < 32; ++k) {
            float4 a0 = *(const float4*)(ATs + k*ASR + r0);
            float4 a1 = *(const float4*)(ATs + k*ASR + r0 + 4);
            ulonglong2 bq = *(const ulonglong2*)(SWA + k*128 + c0);
            float av[8] = {a0.x,a0.y,a0.z,a0.w,a1.x,a1.y,a1.z,a1.w};
            #pragma unroll
            for (int i = 0; i < 8; ++i) {
                u64 aa = bcast2(av[i]);
                fma2(acc2[i][0], aa, bq.x);
                fma2(acc2[i][1], aa, bq.y);
            }
        }
    } else {
        #pragma unroll 1
        for (int s = 0; s < 4; ++s) mma_g1step3(c, aX[s], MW0, s, n8b, L);
    }
    __syncthreads();   // B1a (MWB0 free)
    for (int i = tid; i < 2048; i += NTHREADS) cp16(sb + (OFF_MWB0 << 2) + i * 16, g_w2img + i * 4);  // W2q0
    CP_COMMIT();

    // ================= GEMM1 part b (k 32..63) =================
    if (is_s) {
        #pragma unroll 4
        for (int k = 32; k < 64; ++k) {
            float4 a0 = *(const float4*)(ATs + k*ASR + r0);
            float4 a1 = *(const float4*)(ATs + k*ASR + r0 + 4);
            ulonglong2 bq = *(const ulonglong2*)(SWA + k*128 + c0);
            float av[8] = {a0.x,a0.y,a0.z,a0.w,a1.x,a1.y,a1.z,a1.w};
            #pragma unroll
            for (int i = 0; i < 8; ++i) {
                u64 aa = bcast2(av[i]);
                fma2(acc2[i][0], aa, bq.x);
                fma2(acc2[i][1], aa, bq.y);
            }
        }
        // scalar h1 epilogue -> CTs
        #pragma unroll
        for (int jp = 0; jp < 2; ++jp) {
            int cc = c0 + 2*jp;
            float bias0 = B1s[cc], bias1 = B1s[cc+1];
            float v0[8], v1[8];
            #pragma unroll
            for (int i = 0; i < 8; ++i) {
                float x, y; unpack2(acc2[i][jp], x, y);
                v0[i] = fmaxf(x + bias0, 0.f);
                v1[i] = fmaxf(y + bias1, 0.f);
            }
            *(float4*)(CTs + cc*CS + r0)       = make_float4(v0[0],v0[1],v0[2],v0[3]);
            *(float4*)(CTs + cc*CS + r0 + 4)   = make_float4(v0[4],v0[5],v0[6],v0[7]);
            *(float4*)(CTs + (cc+1)*CS + r0)     = make_float4(v1[0],v1[1],v1[2],v1[3]);
            *(float4*)(CTs + (cc+1)*CS + r0 + 4) = make_float4(v1[4],v1[5],v1[6],v1[7]);
        }
    } else {
        #pragma unroll 1
        for (int s = 0; s < 4; ++s) mma_g1step3(c, aX[4 + s], MW1, s, n8b, L);
        // mma h1 epilogue -> CTs (transposed scalar stores)
        int r = rowb + (L >> 2);
        #pragma unroll
        for (int i = 0; i < 8; ++i) {
            int cb = (n8b + i) * 8 + 2 * (L & 3);
            float bb0 = B1s[cb], bb1 = B1s[cb + 1];
            CTs[cb*CS + r]       = fmaxf(c[i][0] + bb0, 0.f);
            CTs[(cb+1)*CS + r]   = fmaxf(c[i][1] + bb1, 0.f);
            CTs[cb*CS + r + 8]     = fmaxf(c[i][2] + bb0, 0.f);
            CTs[(cb+1)*CS + r + 8] = fmaxf(c[i][3] + bb1, 0.f);
        }
    }
    CP_WAIT0();
    __syncthreads();   // B1b (ATs free, MWB1 free, W2q0 ready)
    for (int i = tid; i < 2048; i += NTHREADS) cp16(sb + (OFF_MWB1 << 2) + i * 16, g_w2img + 8192 + i * 4);  // W2q1
    for (int i = tid; i < 2048; i += NTHREADS) cp16(sb + (OFF_SWA << 2) + i * 16, W2g + 8192 + i * 4);       // W2h1 fp32
    for (int i = tid; i < 1024; i += NTHREADS) {  // scalar W3 pack [k][32]
        int k = i >> 3, cc = i & 7;
        uint32_t dst = sb + (OFF_ATS << 2) + (k * 32 + ((cc & 3) << 2) + ((cc >> 2) << 4)) * 4;
        const float* src = (cc < 4) ? (Wmu + k * 16 + ((cc & 3) << 2))
                                    : (Wlv + k * 16 + ((cc & 3) << 2));
        cp16(dst, src);
    }
    CP_COMMIT();

    // reset accumulators for GEMM2
    #pragma unroll
    for (int i = 0; i < 8; ++i) { acc2[i][0] = 0ULL; acc2[i][1] = 0ULL; }
    #pragma unroll
    for (int i = 0; i < 8; ++i) { c[i][0] = c[i][1] = c[i][2] = c[i][3] = 0.f; }

    // ================= GEMM2 in 4 k-quarters =================
    // q0: k 0..31 (scalar SWBB, mma MWB0)
    if (is_s) {
        #pragma unroll 4
        for (int k = 0; k < 32; ++k) {
            float4 a0 = *(const float4*)(CTs + k*CS + r0);
            float4 a1 = *(const float4*)(CTs + k*CS + r0 + 4);
            ulonglong2 bq = *(const ulonglong2*)(SWBB + k*128 + c0);
            float av[8] = {a0.x,a0.y,a0.z,a0.w,a1.x,a1.y,a1.z,a1.w};
            #pragma unroll
            for (int i = 0; i < 8; ++i) {
                u64 aa = bcast2(av[i]);
                fma2(acc2[i][0], aa, bq.x);
                fma2(acc2[i][1], aa, bq.y);
            }
        }
    } else {
        #pragma unroll 1
        for (int s = 0; s < 4; ++s) mma_step3(c, CTs, MW0, s, s, rowb, n8b, L, 16, 8);
    }
    CP_WAIT0();
    __syncthreads();   // B2a
    for (int i = tid; i < 2048; i += NTHREADS) cp16(sb + (OFF_MWB0 << 2) + i * 16, g_w2img + 16384 + i * 4);  // W2q2
    CP_COMMIT();

    // q1: k 32..63 (scalar SWBB, mma MWB1)
    if (is_s) {
        #pragma unroll 4
        for (int k = 32; k < 64; ++k) {
            float4 a0 = *(const float4*)(CTs + k*CS + r0);
            float4 a1 = *(const float4*)(CTs + k*CS + r0 + 4);
            ulonglong2 bq = *(const ulonglong2*)(SWBB + k*128 + c0);
            float av[8] = {a0.x,a0.y,a0.z,a0.w,a1.x,a1.y,a1.z,a1.w};
            #pragma unroll
            for (int i = 0; i < 8; ++i) {
                u64 aa = bcast2(av[i]);
                fma2(acc2[i][0], aa, bq.x);
                fma2(acc2[i][1], aa, bq.y);
            }
        }
    } else {
        #pragma unroll 1
        for (int s = 0; s < 4; ++s) mma_step3(c, CTs, MW1, s, 4 + s, rowb, n8b, L, 16, 8);
    }
    CP_WAIT0();
    __syncthreads();   // B2b
    for (int i = tid; i < 2048; i += NTHREADS) cp16(sb + (OFF_MWB1 << 2) + i * 16, g_w2img + 24576 + i * 4);  // W2q3
    CP_COMMIT();

    // q2: k 64..95 (scalar SWA, mma MWB0)
    if (is_s) {
        #pragma unroll 4
        for (int k = 64; k < 96; ++k) {
            float4 a0 = *(const float4*)(CTs + k*CS + r0);
            float4 a1 = *(const float4*)(CTs + k*CS + r0 + 4);
            ulonglong2 bq = *(const ulonglong2*)(SWA + (k-64)*128 + c0);
            float av[8] = {a0.x,a0.y,a0.z,a0.w,a1.x,a1.y,a1.z,a1.w};
            #pragma unroll
            for (int i = 0; i < 8; ++i) {
                u64 aa = bcast2(av[i]);
                fma2(acc2[i][0], aa, bq.x);
                fma2(acc2[i][1], aa, bq.y);
            }
        }
    } else {
        #pragma unroll 1
        for (int s = 0; s < 4; ++s) mma_step3(c, CTs, MW0, s, 8 + s, rowb, n8b, L, 16, 8);
    }
    CP_WAIT0();
    __syncthreads();   // B2c
    for (int i = tid; i < 2048; i += NTHREADS) cp16(sb + (OFF_MWB0 << 2) + i * 16, g_w3img + i * 4);  // W3img
    CP_COMMIT();

    // q3: k 96..127 (scalar SWA, mma MWB1) + h2 epilogues
    if (is_s) {
        #pragma unroll 4
        for (int k = 96; k < 128; ++k) {
            float4 a0 = *(const float4*)(CTs + k*CS + r0);
            float4 a1 = *(const float4*)(CTs + k*CS + r0 + 4);
            ulonglong2 bq = *(const ulonglong2*)(SWA + (k-64)*128 + c0);
            float av[8] = {a0.x,a0.y,a0.z,a0.w,a1.x,a1.y,a1.z,a1.w};
            #pragma unroll
            for (int i = 0; i < 8; ++i) {
                u64 aa = bcast2(av[i]);
                fma2(acc2[i][0], aa, bq.x);
                fma2(acc2[i][1], aa, bq.y);
            }
        }
    } else {
        #pragma unroll 1
        for (int s = 0; s < 4; ++s) mma_step3(c, CTs, MW1, s, 12 + s, rowb, n8b, L, 16, 8);
    }
    __syncthreads();   // B2d: all h1 reads of CTs done before overwrite
    if (is_s) {
        #pragma unroll
        for (int jp = 0; jp < 2; ++jp) {
            int cc = c0 + 2*jp;
            float bias0 = B2s[cc], bias1 = B2s[cc+1];
            float v0[8], v1[8];
            #pragma unroll
            for (int i = 0; i < 8; ++i) {
                float x, y; unpack2(acc2[i][jp], x, y);
                v0[i] = fmaxf(x + bias0, 0.f);
                v1[i] = fmaxf(y + bias1, 0.f);
            }
            *(float4*)(CTs + cc*CS + r0)       = make_float4(v0[0],v0[1],v0[2],v0[3]);
            *(float4*)(CTs + cc*CS + r0 + 4)   = make_float4(v0[4],v0[5],v0[6],v0[7]);
            *(float4*)(CTs + (cc+1)*CS + r0)     = make_float4(v1[0],v1[1],v1[2],v1[3]);
            *(float4*)(CTs + (cc+1)*CS + r0 + 4) = make_float4(v1[4],v1[5],v1[6],v1[7]);
        }
    } else {
        int r = rowb + (L >> 2);
        #pragma unroll
        for (int i = 0; i < 8; ++i) {
            int cb = (n8b + i) * 8 + 2 * (L & 3);
            float bb0 = B2s[cb], bb1 = B2s[cb + 1];
            CTs[cb*CS + r]       = fmaxf(c[i][0] + bb0, 0.f);
            CTs[(cb+1)*CS + r]   = fmaxf(c[i][1] + bb1, 0.f);
            CTs[cb*CS + r + 8]     = fmaxf(c[i][2] + bb0, 0.f);
            CTs[(cb+1)*CS + r + 8] = fmaxf(c[i][3] + bb1, 0.f);
        }
    }
    CP_WAIT0();
    __syncthreads();   // B3 (W3img ready, SWB region dead -> aliases live)
    for (int i = tid; i < 1024; i += NTHREADS) cp16(sb + (OFF_MWB1 << 2) + i * 16, codebook + i * 4);  // CB
    CP_COMMIT();

    // ================= GEMM3 =================
    if (is_s) {
        // 256 threads: colpair cp=tid&15 -> cols 2cp,2cp+1 ; rowgrp=(tid>>4) -> 4 rows
        int cp = tid & 15;
        int c3 = 2 * cp;
        int rr0 = (tid >> 4) * 4;      // 0..60
        u64 acc3[4];
        #pragma unroll
        for (int i = 0; i < 4; ++i) acc3[i] = 0ULL;
        #pragma unroll 4
        for (int k = 0; k < 128; ++k) {
            float4 a0 = *(const float4*)(CTs + k*CS + rr0);
            u64 wp = *(const u64*)(W3S + k*32 + c3);
            float av[4] = {a0.x, a0.y, a0.z, a0.w};
            #pragma unroll
            for (int i = 0; i < 4; ++i) {
                u64 aa = bcast2(av[i]);
                fma2(acc3[i], aa, wp);
            }
        }
        float bias0 = BMLs[c3], bias1 = BMLs[c3 + 1];
        #pragma unroll
        for (int i = 0; i < 4; ++i) {
            float x, y; unpack2(acc3[i], x, y);
            MLB[(rr0 + i)*33 + c3]     = x + bias0;
            MLB[(rr0 + i)*33 + c3 + 1] = y + bias1;
        }
    } else {
        float c3f[8][4];
        #pragma unroll
        for (int i = 0; i < 2; ++i) { c3f[i][0] = c3f[i][1] = c3f[i][2] = c3f[i][3] = 0.f; }
        int n8b3 = (mw & 1) * 2;
        #pragma unroll 1
        for (int s = 0; s < 16; ++s) mma_step3(c3f, CTs, MW0, s, s, rowb, n8b3, L, 4, 2);
        int r = rowb + (L >> 2);
        #pragma unroll
        for (int i = 0; i < 2; ++i) {
            int cb = (n8b3 + i) * 8 + 2 * (L & 3);
            float bb0 = BMLs[cb], bb1 = BMLs[cb + 1];
            MLB[r*33 + cb]       = c3f[i][0] + bb0;
            MLB[r*33 + cb + 1]   = c3f[i][1] + bb1;
            MLB[(r+8)*33 + cb]     = c3f[i][2] + bb0;
            MLB[(r+8)*33 + cb + 1] = c3f[i][3] + bb1;
        }
    }
    CP_WAIT0();
    __syncthreads();   // B4 (CB ready, MLB complete)

    // ---- z-stage (all 128 rows) + mu/lv gmem writes ; CN compute ----
    if (tid < 256) {
        int row = tid >> 1;
        int d0  = (tid & 1) << 3;
        size_t g = (size_t)(row0 + row) * D_Z + d0;
        float4 e0 = *(const float4*)(eps + g);
        float4 e1 = *(const float4*)(eps + g + 4);
        float ev[8] = {e0.x,e0.y,e0.z,e0.w,e1.x,e1.y,e1.z,e1.w};
        float mu[8], lv[8], zv[8];
        #pragma unroll
        for (int q = 0; q < 8; ++q) {
            mu[q] = MLB[row*33 + d0 + q];
            lv[q] = MLB[row*33 + 16 + d0 + q];
            zv[q] = fmaf(ev[q], expf(0.5f * lv[q]), mu[q]);
        }
        *(float4*)(outMu + g)     = make_float4(mu[0],mu[1],mu[2],mu[3]);
        *(float4*)(outMu + g + 4) = make_float4(mu[4],mu[5],mu[6],mu[7]);
        *(float4*)(outLv + g)     = make_float4(lv[0],lv[1],lv[2],lv[3]);
        *(float4*)(outLv + g + 4) = make_float4(lv[4],lv[5],lv[6],lv[7]);
        *(float4*)(outZ + g)      = make_float4(zv[0],zv[1],zv[2],zv[3]);
        *(float4*)(outZ + g + 4)  = make_float4(zv[4],zv[5],zv[6],zv[7]);
        *(float4*)(ZS + row*20 + d0)     = make_float4(zv[0],zv[1],zv[2],zv[3]);
        *(float4*)(ZS + row*20 + d0 + 4) = make_float4(zv[4],zv[5],zv[6],zv[7]);
    } else {
        int cc = tid - 256;
        const float4* c4 = (const float4*)(CBs + cc * D_Z);
        float4 q0 = c4[0], q1 = c4[1], q2 = c4[2], q3 = c4[3];
        CNs[cc] = q0.x*q0.x + q0.y*q0.y + q0.z*q0.z + q0.w*q0.w
                + q1.x*q1.x + q1.y*q1.y + q1.z*q1.z + q1.w*q1.w
                + q2.x*q2.x + q2.y*q2.y + q2.z*q2.z + q2.w*q2.w
                + q3.x*q3.x + q3.y*q3.y + q3.z*q3.z + q3.w*q3.w;
    }
    __syncthreads();   // B5

    // ---- VQ dist: 4 quarters of 64 codes ----
    {
        int row = tid & 127;
        int qr  = tid >> 7;
        u64 zp[8];
        #pragma unroll
        for (int q = 0; q < 8; ++q) zp[q] = *(const u64*)(ZS + row*20 + 2*q);
        float best = 3.4e38f, sec = 3.4e38f;
        int bi = 0;
        int cbase = qr * 64;
        for (int cc = 0; cc < 64; ++cc) {
            const ulonglong2* q2p = (const ulonglong2*)(CBs + (cbase + cc) * D_Z);
            ulonglong2 qa = q2p[0], qb = q2p[1];
            u64 dp = 0ULL;
            fma2(dp, zp[0], qa.x); fma2(dp, zp[1], qa.y);
            fma2(dp, zp[2], qb.x); fma2(dp, zp[3], qb.y);
            ulonglong2 qc = q2p[2], qd = q2p[3];
            fma2(dp, zp[4], qc.x); fma2(dp, zp[5], qc.y);
            fma2(dp, zp[6], qd.x); fma2(dp, zp[7], qd.y);
            float dx, dy; unpack2(dp, dx, dy);
            float score = fmaf(-2.f, dx + dy, CNs[cbase + cc]);
            if (score < best) { sec = best; best = score; bi = cbase + cc; }
            else if (score < sec) { sec = score; }
        }
        REDs[tid] = best;
        SECs[tid] = sec;
        REDi[tid] = bi;
    }
    __syncthreads();   // B6

    float ss = 0.f;
    if (tid < 128) {
        int row = tid;
        float best = REDs[row], sec = SECs[row];
        int idx = REDi[row];
        #pragma unroll
        for (int q = 1; q < 4; ++q) {
            float b2 = REDs[q*128 + row];
            if (b2 < best) { sec = fminf(best, SECs[q*128 + row]); best = b2; idx = REDi[q*128 + row]; }
            else           { sec = fminf(sec, fminf(b2, SECs[q*128 + row])); }
        }
        size_t g = (size_t)(row0 + row) * D_Z;
        bool flag = (row >= 64) && ((sec - best) < MARGIN);
        if (flag) {
            int slot = atomicAdd(&g_fixcount, 1);
            g_fixlist[slot] = row0 + row;
            #pragma unroll
            for (int q4 = 0; q4 < 4; ++q4)
                *(float4*)(outZq + g + q4*4) = *(const float4*)(CBs + idx*D_Z + q4*4);
        } else {
            #pragma unroll
            for (int q4 = 0; q4 < 4; ++q4) {
                float4 qc = *(const float4*)(CBs + idx*D_Z + q4*4);
                float4 zz = *(const float4*)(ZS + row*20 + q4*4);
                float d0 = qc.x - zz.x, d1 = qc.y - zz.y, d2 = qc.z - zz.z, d3 = qc.w - zz.w;
                ss = fmaf(d0, d0, ss); ss = fmaf(d1, d1, ss);
                ss = fmaf(d2, d2, ss); ss = fmaf(d3, d3, ss);
                *(float4*)(outZq + g + q4*4) = qc;
            }
        }
    }
    __syncthreads();
    if (tid < 128) REDs[tid] = ss;
    __syncthreads();
    #pragma unroll
    for (int s = 64; s > 0; s >>= 1) {
        if (tid < s) REDs[tid] += REDs[tid + s];
        __syncthreads();
    }
    if (tid == 0) g_partial[tile] = REDs[0];
}

// ---- exact scalar recompute for flagged rows (validated in R8) ----
__global__ void fixup_kernel(const float* __restrict__ feats,
                             const float* __restrict__ W1,  const float* __restrict__ b1,
                             const float* __restrict__ W2,  const float* __restrict__ b2,
                             const float* __restrict__ Wmu, const float* __restrict__ bmu,
                             const float* __restrict__ Wlv, const float* __restrict__ blv,
                             const float* __restrict__ codebook, const float* __restrict__ eps,
                             float* __restrict__ outZ,  float* __restrict__ outMu,
                             float* __restrict__ outLv, float* __restrict__ outZq)
{
    int gw = (blockIdx.x * blockDim.x + threadIdx.x) >> 5;
    int L  = threadIdx.x & 31;
    int nw = (gridDim.x * blockDim.x) >> 5;
    int cnt = g_fixcount;
    for (int it = gw; it < cnt; it += nw) {
        int row = g_fixlist[it];
        const float* x = feats + (size_t)row * D_IN;
        float h1[4], h2[4];
        #pragma unroll
        for (int j = 0; j < 4; ++j) {
            int col = L + 32 * j;
            float acc = 0.f;
            for (int k = 0; k < 64; ++k) acc = fmaf(x[k], W1[k * 128 + col], acc);
            h1[j] = fmaxf(acc + b1[col], 0.f);
        }
        #pragma unroll
        for (int j = 0; j < 4; ++j) {
            int col = L + 32 * j;
            float acc = 0.f;
            for (int k = 0; k < 128; ++k) {
                float v = __shfl_sync(0xffffffffu, h1[k >> 5], k & 31);
                acc = fmaf(v, W2[k * 128 + col], acc);
            }
            h2[j] = fmaxf(acc + b2[col], 0.f);
        }
        float acc3 = 0.f;
        for (int k = 0; k < 128; ++k) {
            float v = __shfl_sync(0xffffffffu, h2[k >> 5], k & 31);
            float wv = (L < 16) ? Wmu[k * 16 + L] : Wlv[k * 16 + (L - 16)];
            acc3 = fmaf(v, wv, acc3);
        }
        float mulv = acc3 + ((L < 16) ? bmu[L] : blv[L - 16]);
        int d = L & 15;
        float muv = __shfl_sync(0xffffffffu, mulv, d);
        float lvv = __shfl_sync(0xffffffffu, mulv, d + 16);
        float z_d = fmaf(eps[(size_t)row * D_Z + d], expf(0.5f * lvv), muv);
        if (L < 16) { outMu[(size_t)row * D_Z + L] = mulv; outZ[(size_t)row * D_Z + L] = z_d; }
        else        { outLv[(size_t)row * D_Z + (L - 16)] = mulv; }
        float z[16];
        #pragma unroll
        for (int d2 = 0; d2 < 16; ++d2) z[d2] = __shfl_sync(0xffffffffu, z_d, d2);
        float best = 3.4e38f; int bi = 0;
        for (int t = 0; t < 8; ++t) {
            int cc = L * 8 + t;
            const float* q = codebook + cc * D_Z;
            float dx = 0.f, dy = 0.f;
            #pragma unroll
            for (int d2 = 0; d2 < 16; d2 += 2) {
                dx = fmaf(z[d2], q[d2], dx);
                dy = fmaf(z[d2 + 1], q[d2 + 1], dy);
            }
            float cn = q[0]*q[0] + q[1]*q[1] + q[2]*q[2] + q[3]*q[3]
                     + q[4]*q[4] + q[5]*q[5] + q[6]*q[6] + q[7]*q[7]
                     + q[8]*q[8] + q[9]*q[9] + q[10]*q[10] + q[11]*q[11]
                     + q[12]*q[12] + q[13]*q[13] + q[14]*q[14] + q[15]*q[15];
            float score = fmaf(-2.f, dx + dy, cn);
            if (score < best) { best = score; bi = cc; }
        }
        #pragma unroll
        for (int off = 16; off > 0; off >>= 1) {
            float so = __shfl_xor_sync(0xffffffffu, best, off);
            int   io = __shfl_xor_sync(0xffffffffu, bi, off);
            if (so < best || (so == best && io < bi)) { best = so; bi = io; }
        }
        float ssl = 0.f;
        if (L < 16) {
            float qv = codebook[bi * D_Z + L];
            outZq[(size_t)row * D_Z + L] = qv;
            float dd = qv - z_d;
            ssl = dd * dd;
        }
        #pragma unroll
        for (int off = 16; off > 0; off >>= 1) ssl += __shfl_xor_sync(0xffffffffu, ssl, off);
        if (L == 0) atomicAdd(&g_fixloss, ssl);
    }
}

__global__ void loss_kernel(float* __restrict__ out_loss)
{
    __shared__ float s[1024];
    float v = 0.f;
    for (int i = threadIdx.x; i < NTILES; i += 1024) v += g_partial[i];
    s[threadIdx.x] = v;
    __syncthreads();
    #pragma unroll
    for (int st = 512; st > 0; st >>= 1) {
        if (threadIdx.x < st) s[threadIdx.x] += s[threadIdx.x + st];
        __syncthreads();
    }
    if (threadIdx.x == 0) {
        float m = (s[0] + g_fixloss) / (float)((long long)N_ROWS * D_Z);
        out_loss[0] = 0.25f * (m + m);
    }
}

extern "C" void kernel_launch(void* const* d_in, const int* in_sizes, int n_in,
                              void* d_out, int out_size)
{
    const float* feats    = (const float*)d_in[0];
    const float* W1       = (const float*)d_in[1];
    const float* b1       = (const float*)d_in[2];
    const float* W2       = (const float*)d_in[3];
    const float* b2       = (const float*)d_in[4];
    const float* Wmu      = (const float*)d_in[5];
    const float* bmu      = (const float*)d_in[6];
    const float* Wlv      = (const float*)d_in[7];
    const float* blv      = (const float*)d_in[8];
    const float* codebook = (const float*)d_in[9];
    const float* eps      = (const float*)d_in[10];

    float* out = (float*)d_out;
    size_t sec = (size_t)N_ROWS * D_Z;

    setup_kernel<<<32, 256>>>(W1, W2, Wmu, Wlv);

    cudaFuncSetAttribute(enc_kernel, cudaFuncAttributeMaxDynamicSharedMemorySize, SMEM_BYTES);
    enc_kernel<<<NTILES, NTHREADS, SMEM_BYTES>>>(
        feats, W1, b1, W2, b2, Wmu, bmu, Wlv, blv, codebook, eps,
        out, out + sec, out + 2 * sec, out + 3 * sec);

    fixup_kernel<<<256, 256>>>(feats, W1, b1, W2, b2, Wmu, bmu, Wlv, blv,
                               codebook, eps,
                               out, out + sec, out + 2 * sec, out + 3 * sec);

    loss_kernel<<<1, 1024>>>(out + 4 * sec);
}

// round 14
// speedup vs baseline: 1.0009x; 1.0009x over previous
#include <cuda_runtime.h>
#include <math.h>
#include <stdint.h>

#define N_ROWS   524288
#define D_IN     64
#define H_DIM    128
#define D_Z      16
#define K_CODES  256
#define TILE_M   128
#define NTHREADS 512
#define NTILES   (N_ROWS / TILE_M)

#define CS   132      // CTs row stride (floats)
#define ASR  68       // ATs row stride
#define MARGIN 0.02f

// ---- smem layout (float offsets) ----
#define OFF_ATS  0            // 4352 ; alias W3S (4096) after G1
#define OFF_CTS  4352         // 16896 = 128 cols * 132
#define OFF_SWB  21248        // 16384 : A @ +0 (8192), B @ +8192
#define OFF_SWA  21248
#define OFF_SWBB 29440
// aliases into SWB region (dead after B3):
#define OFF_ZS   21248        // 2560
#define OFF_MLB  23808        // 4224 (128 rows * 33)
#define OFF_CN   28032        // 256
#define OFF_RED  28288        // 512
#define OFF_SEC  28800        // 512
#define OFF_REDI 29312        // 512
#define OFF_MWB0 37632        // 8192 (32KB)
#define OFF_MWB1 45824        // 8192 (32KB)
#define OFF_B1S  54016        // 128
#define OFF_B2S  54144        // 128
#define OFF_BML  54272        // 32
#define SMEM_FLOATS 54304
#define SMEM_BYTES  (SMEM_FLOATS * 4)   // 217216

typedef unsigned long long u64;

// mma weight images (hi/lo split, fragment-ordered)
__device__ __align__(16) float g_w1img[16384];   // 2 halves x 2048 float4
__device__ __align__(16) float g_w2img[32768];   // 4 quarters x 2048 float4
__device__ __align__(16) float g_w3img[8192];    // 2048 float4
__device__ float g_partial[NTILES];
__device__ int   g_fixcount;
__device__ float g_fixloss;
__device__ int   g_fixlist[N_ROWS];

// ---- helpers ----
__device__ __forceinline__ uint32_t smem_u32(const void* p) {
    uint32_t a;
    asm("{ .reg .u64 t; cvta.to.shared.u64 t, %1; cvt.u32.u64 %0, t; }" : "=r"(a) : "l"(p));
    return a;
}
__device__ __forceinline__ void split32(float v, uint32_t& h, uint32_t& l) {
    asm("cvt.rna.tf32.f32 %0, %1;" : "=r"(h) : "f"(v));
    float hf = __uint_as_float(h);
    asm("cvt.rna.tf32.f32 %0, %1;" : "=r"(l) : "f"(v - hf));
}
__device__ __forceinline__ void mma8(float* c, uint32_t a0, uint32_t a1, uint32_t a2, uint32_t a3,
                                     uint32_t b0, uint32_t b1) {
    asm volatile("mma.sync.aligned.m16n8k8.row.col.f32.tf32.tf32.f32 "
                 "{%0,%1,%2,%3},{%4,%5,%6,%7},{%8,%9},{%0,%1,%2,%3};"
                 : "+f"(c[0]), "+f"(c[1]), "+f"(c[2]), "+f"(c[3])
                 : "r"(a0), "r"(a1), "r"(a2), "r"(a3), "r"(b0), "r"(b1));
}
__device__ __forceinline__ void cp16(uint32_t dst, const void* src) {
    asm volatile("cp.async.cg.shared.global [%0], [%1], 16;" :: "r"(dst), "l"(src) : "memory");
}
#define CP_COMMIT() asm volatile("cp.async.commit_group;" ::: "memory")
#define CP_WAIT0()  asm volatile("cp.async.wait_group 0;" ::: "memory")

__device__ __forceinline__ u64 bcast2(float x) { u64 r; asm("mov.b64 %0, {%1, %1};" : "=l"(r) : "f"(x)); return r; }
__device__ __forceinline__ void unpack2(u64 v, float& x, float& y) { asm("mov.b64 {%0, %1}, %2;" : "=f"(x), "=f"(y) : "l"(v)); }
__device__ __forceinline__ void fma2(u64& d, u64 a, u64 b) { asm("fma.rn.f32x2 %0, %1, %2, %3;" : "=l"(d) : "l"(a), "l"(b), "l"(d)); }

// ---- setup: split weight images + reset fix state ----
__global__ void setup_kernel(const float* __restrict__ W1, const float* __restrict__ W2,
                             const float* __restrict__ Wmu, const float* __restrict__ Wlv)
{
    if (blockIdx.x == 0 && threadIdx.x == 0) { g_fixcount = 0; g_fixloss = 0.f; }
    int t = blockIdx.x * blockDim.x + threadIdx.x;
    int nt = gridDim.x * blockDim.x;
    // W1img: 2 halves (k 0-31, 32-63), each 2048 float4
    for (int e = t; e < 4096; e += nt) {
        int h = e >> 11, f = e & 2047;
        int sl = f >> 9, n8 = (f >> 5) & 15, L = f & 31;
        int k0 = h * 32 + sl * 8 + (L & 3), n = n8 * 8 + (L >> 2);
        uint32_t h0, l0, h1, l1;
        split32(W1[k0 * 128 + n], h0, l0);
        split32(W1[(k0 + 4) * 128 + n], h1, l1);
        ((float4*)g_w1img)[e] = make_float4(__uint_as_float(h0), __uint_as_float(h1),
                                            __uint_as_float(l0), __uint_as_float(l1));
    }
    // W2img: 4 quarters (k 0-31, 32-63, 64-95, 96-127)
    for (int e = t; e < 8192; e += nt) {
        int q = e >> 11, f = e & 2047;
        int sl = f >> 9, n8 = (f >> 5) & 15, L = f & 31;
        int k0 = q * 32 + sl * 8 + (L & 3), n = n8 * 8 + (L >> 2);
        uint32_t h0, l0, h1, l1;
        split32(W2[k0 * 128 + n], h0, l0);
        split32(W2[(k0 + 4) * 128 + n], h1, l1);
        ((float4*)g_w2img)[e] = make_float4(__uint_as_float(h0), __uint_as_float(h1),
                                            __uint_as_float(l0), __uint_as_float(l1));
    }
    // W3img: [Wmu|Wlv] 128k x 32n: 16 s x 4 n8
    for (int f = t; f < 2048; f += nt) {
        int s = f >> 7, n8 = (f >> 5) & 3, L = f & 31;
        int k0 = s * 8 + (L & 3), n = n8 * 8 + (L >> 2);
        float b0 = (n < 16) ? Wmu[k0 * 16 + n] : Wlv[k0 * 16 + n - 16];
        float b1 = (n < 16) ? Wmu[(k0 + 4) * 16 + n] : Wlv[(k0 + 4) * 16 + n - 16];
        uint32_t h0, l0, h1, l1;
        split32(b0, h0, l0); split32(b1, h1, l1);
        ((float4*)g_w3img)[f] = make_float4(__uint_as_float(h0), __uint_as_float(h1),
                                            __uint_as_float(l0), __uint_as_float(l1));
    }
}

// mma 3-term k-step, A from CTs (transposed [col][row])
__device__ __forceinline__ void mma_step3(float (*c)[4], const float* CTs, const uint4* img,
                                          int s_local, int kglob, int rowb, int n8base,
                                          int L, int NTIMG, int NT8)
{
    int k0 = kglob * 8 + (L & 3);
    int r  = rowb + (L >> 2);
    float a0v = CTs[k0 * CS + r];
    float a1v = CTs[k0 * CS + r + 8];
    float a2v = CTs[(k0 + 4) * CS + r];
    float a3v = CTs[(k0 + 4) * CS + r + 8];
    uint32_t ah0, al0, ah1, al1, ah2, al2, ah3, al3;
    split32(a0v, ah0, al0); split32(a1v, ah1, al1);
    split32(a2v, ah2, al2); split32(a3v, ah3, al3);
    #pragma unroll
    for (int i = 0; i < 8; ++i) {
        if (i >= NT8) break;
        uint4 B = img[(s_local * NTIMG + n8base + i) * 32 + L];
        mma8(c[i], ah0, ah1, ah2, ah3, B.x, B.y);
        mma8(c[i], ah0, ah1, ah2, ah3, B.z, B.w);
        mma8(c[i], al0, al1, al2, al3, B.x, B.y);
    }
}

// mma 3-term k-step, A from registers (GEMM1)
__device__ __forceinline__ void mma_g1step3(float (*c)[4], const float* aXs, const uint4* img,
                                            int s_local, int n8base, int L)
{
    uint32_t ah0, al0, ah1, al1, ah2, al2, ah3, al3;
    split32(aXs[0], ah0, al0); split32(aXs[1], ah1, al1);
    split32(aXs[2], ah2, al2); split32(aXs[3], ah3, al3);
    #pragma unroll
    for (int i = 0; i < 8; ++i) {
        uint4 B = img[(s_local * 16 + n8base + i) * 32 + L];
        mma8(c[i], ah0, ah1, ah2, ah3, B.x, B.y);
        mma8(c[i], ah0, ah1, ah2, ah3, B.z, B.w);
        mma8(c[i], al0, al1, al2, al3, B.x, B.y);
    }
}

__global__ __launch_bounds__(NTHREADS, 1)
void enc_kernel(const float* __restrict__ feats,
                const float* __restrict__ W1g,  const float* __restrict__ b1,
                const float* __restrict__ W2g,  const float* __restrict__ b2,
                const float* __restrict__ Wmu, const float* __restrict__ bmu,
                const float* __restrict__ Wlv, const float* __restrict__ blv,
                const float* __restrict__ codebook, const float* __restrict__ eps,
                float* __restrict__ outZ,  float* __restrict__ outMu,
                float* __restrict__ outLv, float* __restrict__ outZq)
{
    extern __shared__ float sm[];
    const uint32_t sb = smem_u32(sm);
    const int tid = threadIdx.x;
    const int w   = tid >> 5;
    const int L   = tid & 31;
    const int tile = blockIdx.x;
    const int row0 = tile * TILE_M;

    float* ATs  = sm + OFF_ATS;
    float* W3S  = sm + OFF_ATS;      // alias after G1
    float* CTs  = sm + OFF_CTS;
    float* SWA  = sm + OFF_SWA;
    float* SWBB = sm + OFF_SWBB;
    float* ZS   = sm + OFF_ZS;
    float* MLB  = sm + OFF_MLB;
    float* CNs  = sm + OFF_CN;
    float* REDs = sm + OFF_RED;
    float* SECs = sm + OFF_SEC;
    int*   REDi = (int*)(sm + OFF_REDI);
    float* B1s  = sm + OFF_B1S;
    float* B2s  = sm + OFF_B2S;
    float* BMLs = sm + OFF_BML;
    const uint4* MW0 = (const uint4*)(sm + OFF_MWB0);
    const uint4* MW1 = (const uint4*)(sm + OFF_MWB1);
    const float* CBs = sm + OFF_MWB1;   // codebook lands in MWB1 at the end

    const bool is_s = (w < 8);
    const int  mw   = w - 8;                       // mma warp id 0..7
    const int  rowb = 64 + ((mw >> 1) & 3) * 16;   // mma rows
    const int  n8b  = (mw & 1) * 8;                // mma col half

    // scalar mapping
    const int stx = tid & 31;
    const int sty = tid >> 5;        // 0..7 for scalar threads
    const int r0  = sty * 8;
    const int c0  = stx * 4;

    // ---- preload copies ----
    for (int i = tid; i < 2048; i += NTHREADS) cp16(sb + (OFF_SWA << 2) + i * 16, W1g + i * 4);
    for (int i = tid; i < 2048; i += NTHREADS) cp16(sb + (OFF_SWBB << 2) + i * 16, W2g + i * 4);
    for (int i = tid; i < 2048; i += NTHREADS) cp16(sb + (OFF_MWB0 << 2) + i * 16, g_w1img + i * 4);
    for (int i = tid; i < 2048; i += NTHREADS) cp16(sb + (OFF_MWB1 << 2) + i * 16, g_w1img + 8192 + i * 4);
    CP_COMMIT();

    // X transpose (rows 0..63) for scalar half
    {
        const float4* Xg = (const float4*)(feats + (size_t)row0 * D_IN);
        #pragma unroll
        for (int it = 0; it < 2; ++it) {
            int i = tid + it * NTHREADS;   // 0..1023
            float4 v = Xg[i];
            int r  = i >> 4;
            int k0 = (i & 15) << 2;
            ATs[(k0+0)*ASR + r] = v.x;
            ATs[(k0+1)*ASR + r] = v.y;
            ATs[(k0+2)*ASR + r] = v.z;
            ATs[(k0+3)*ASR + r] = v.w;
        }
    }
    // mma X fragments (rows 64..127) from gmem
    float aX[8][4];
    if (!is_s) {
        const float* fb = feats + (size_t)(row0 + rowb + (L >> 2)) * D_IN + (L & 3);
        #pragma unroll
        for (int s = 0; s < 8; ++s) {
            aX[s][0] = fb[s * 8];
            aX[s][1] = fb[512 + s * 8];
            aX[s][2] = fb[s * 8 + 4];
            aX[s][3] = fb[512 + s * 8 + 4];
        }
    }
    if (tid < 128) { B1s[tid] = b1[tid]; B2s[tid] = b2[tid]; }
    if (tid >= 128 && tid < 160) { int q = tid - 128; BMLs[q] = (q < 16) ? bmu[q] : blv[q - 16]; }

    CP_WAIT0();
    __syncthreads();   // B0

    // scalar accumulators
    u64 acc2[8][2];
    #pragma unroll
    for (int i = 0; i < 8; ++i) { acc2[i][0] = 0ULL; acc2[i][1] = 0ULL; }
    // mma accumulators
    float c[8][4];
    #pragma unroll
    for (int i = 0; i < 8; ++i) { c[i][0] = c[i][1] = c[i][2] = c[i][3] = 0.f; }

    // ================= GEMM1 part a (k 0..31) =================
    if (is_s) {
        #pragma unroll 4
        for (int k = 0; k < 32; ++k) {
            float4 a0 = *(const float4*)(ATs + k*ASR + r0);
            float4 a1 = *(const float4*)(ATs + k*ASR + r0 + 4);
            ulonglong2 bq = *(const ulonglong2*)(SWA + k*128 + c0);
            float av[8] = {a0.x,a0.y,a0.z,a0.w,a1.x,a1.y,a1.z,a1.w};
            #pragma unroll
            for (int i = 0; i < 8; ++i) {
                u64 aa = bcast2(av[i]);
                fma2(acc2[i][0], aa, bq.x);
                fma2(acc2[i][1], aa, bq.y);
            }
        }
    } else {
        #pragma unroll 1
        for (int s = 0; s < 4; ++s) mma_g1step3(c, aX[s], MW0, s, n8b, L);
    }
    __syncthreads();   // B1a (MWB0 free)
    for (int i = tid; i < 2048; i += NTHREADS) cp16(sb + (OFF_MWB0 << 2) + i * 16, g_w2img + i * 4);  // W2q0
    CP_COMMIT();

    // ================= GEMM1 part b (k 32..63) =================
    if (is_s) {
        #pragma unroll 4
        for (int k = 32; k < 64; ++k) {
            float4 a0 = *(const float4*)(ATs + k*ASR + r0);
            float4 a1 = *(const float4*)(ATs + k*ASR + r0 + 4);
            ulonglong2 bq = *(const ulonglong2*)(SWA + k*128 + c0);
            float av[8] = {a0.x,a0.y,a0.z,a0.w,a1.x,a1.y,a1.z,a1.w};
            #pragma unroll
            for (int i = 0; i < 8; ++i) {
                u64 aa = bcast2(av[i]);
                fma2(acc2[i][0], aa, bq.x);
                fma2(acc2[i][1], aa, bq.y);
            }
        }
        // scalar h1 epilogue -> CTs
        #pragma unroll
        for (int jp = 0; jp < 2; ++jp) {
            int cc = c0 + 2*jp;
            float bias0 = B1s[cc], bias1 = B1s[cc+1];
            float v0[8], v1[8];
            #pragma unroll
            for (int i = 0; i < 8; ++i) {
                float x, y; unpack2(acc2[i][jp], x, y);
                v0[i] = fmaxf(x + bias0, 0.f);
                v1[i] = fmaxf(y + bias1, 0.f);
            }
            *(float4*)(CTs + cc*CS + r0)       = make_float4(v0[0],v0[1],v0[2],v0[3]);
            *(float4*)(CTs + cc*CS + r0 + 4)   = make_float4(v0[4],v0[5],v0[6],v0[7]);
            *(float4*)(CTs + (cc+1)*CS + r0)     = make_float4(v1[0],v1[1],v1[2],v1[3]);
            *(float4*)(CTs + (cc+1)*CS + r0 + 4) = make_float4(v1[4],v1[5],v1[6],v1[7]);
        }
    } else {
        #pragma unroll 1
        for (int s = 0; s < 4; ++s) mma_g1step3(c, aX[4 + s], MW1, s, n8b, L);
        // mma h1 epilogue -> CTs (transposed scalar stores)
        int r = rowb + (L >> 2);
        #pragma unroll
        for (int i = 0; i < 8; ++i) {
            int cb = (n8b + i) * 8 + 2 * (L & 3);
            float bb0 = B1s[cb], bb1 = B1s[cb + 1];
            CTs[cb*CS + r]       = fmaxf(c[i][0] + bb0, 0.f);
            CTs[(cb+1)*CS + r]   = fmaxf(c[i][1] + bb1, 0.f);
            CTs[cb*CS + r + 8]     = fmaxf(c[i][2] + bb0, 0.f);
            CTs[(cb+1)*CS + r + 8] = fmaxf(c[i][3] + bb1, 0.f);
        }
    }
    CP_WAIT0();
    __syncthreads();   // B1b (ATs free, MWB1 free, W2q0 ready)
    for (int i = tid; i < 2048; i += NTHREADS) cp16(sb + (OFF_MWB1 << 2) + i * 16, g_w2img + 8192 + i * 4);  // W2q1
    for (int i = tid; i < 2048; i += NTHREADS) cp16(sb + (OFF_SWA << 2) + i * 16, W2g + 8192 + i * 4);       // W2h1 fp32
    for (int i = tid; i < 1024; i += NTHREADS) {  // scalar W3 pack [k][32]
        int k = i >> 3, cc = i & 7;
        uint32_t dst = sb + (OFF_ATS << 2) + (k * 32 + ((cc & 3) << 2) + ((cc >> 2) << 4)) * 4;
        const float* src = (cc < 4) ? (Wmu + k * 16 + ((cc & 3) << 2))
                                    : (Wlv + k * 16 + ((cc & 3) << 2));
        cp16(dst, src);
    }
    CP_COMMIT();

    // reset accumulators for GEMM2
    #pragma unroll
    for (int i = 0; i < 8; ++i) { acc2[i][0] = 0ULL; acc2[i][1] = 0ULL; }
    #pragma unroll
    for (int i = 0; i < 8; ++i) { c[i][0] = c[i][1] = c[i][2] = c[i][3] = 0.f; }

    // ================= GEMM2 in 4 k-quarters =================
    // q0: k 0..31 (scalar SWBB, mma MWB0)
    if (is_s) {
        #pragma unroll 4
        for (int k = 0; k < 32; ++k) {
            float4 a0 = *(const float4*)(CTs + k*CS + r0);
            float4 a1 = *(const float4*)(CTs + k*CS + r0 + 4);
            ulonglong2 bq = *(const ulonglong2*)(SWBB + k*128 + c0);
            float av[8] = {a0.x,a0.y,a0.z,a0.w,a1.x,a1.y,a1.z,a1.w};
            #pragma unroll
            for (int i = 0; i < 8; ++i) {
                u64 aa = bcast2(av[i]);
                fma2(acc2[i][0], aa, bq.x);
                fma2(acc2[i][1], aa, bq.y);
            }
        }
    } else {
        #pragma unroll 1
        for (int s = 0; s < 4; ++s) mma_step3(c, CTs, MW0, s, s, rowb, n8b, L, 16, 8);
    }
    CP_WAIT0();
    __syncthreads();   // B2a
    for (int i = tid; i < 2048; i += NTHREADS) cp16(sb + (OFF_MWB0 << 2) + i * 16, g_w2img + 16384 + i * 4);  // W2q2
    CP_COMMIT();

    // q1: k 32..63 (scalar SWBB, mma MWB1)
    if (is_s) {
        #pragma unroll 4
        for (int k = 32; k < 64; ++k) {
            float4 a0 = *(const float4*)(CTs + k*CS + r0);
            float4 a1 = *(const float4*)(CTs + k*CS + r0 + 4);
            ulonglong2 bq = *(const ulonglong2*)(SWBB + k*128 + c0);
            float av[8] = {a0.x,a0.y,a0.z,a0.w,a1.x,a1.y,a1.z,a1.w};
            #pragma unroll
            for (int i = 0; i < 8; ++i) {
                u64 aa = bcast2(av[i]);
                fma2(acc2[i][0], aa, bq.x);
                fma2(acc2[i][1], aa, bq.y);
            }
        }
    } else {
        #pragma unroll 1
        for (int s = 0; s < 4; ++s) mma_step3(c, CTs, MW1, s, 4 + s, rowb, n8b, L, 16, 8);
    }
    CP_WAIT0();
    __syncthreads();   // B2b
    for (int i = tid; i < 2048; i += NTHREADS) cp16(sb + (OFF_MWB1 << 2) + i * 16, g_w2img + 24576 + i * 4);  // W2q3
    CP_COMMIT();

    // q2: k 64..95 (scalar SWA, mma MWB0)
    if (is_s) {
        #pragma unroll 4
        for (int k = 64; k < 96; ++k) {
            float4 a0 = *(const float4*)(CTs + k*CS + r0);
            float4 a1 = *(const float4*)(CTs + k*CS + r0 + 4);
            ulonglong2 bq = *(const ulonglong2*)(SWA + (k-64)*128 + c0);
            float av[8] = {a0.x,a0.y,a0.z,a0.w,a1.x,a1.y,a1.z,a1.w};
            #pragma unroll
            for (int i = 0; i < 8; ++i) {
                u64 aa = bcast2(av[i]);
                fma2(acc2[i][0], aa, bq.x);
                fma2(acc2[i][1], aa, bq.y);
            }
        }
    } else {
        #pragma unroll 1
        for (int s = 0; s < 4; ++s) mma_step3(c, CTs, MW0, s, 8 + s, rowb, n8b, L, 16, 8);
    }
    CP_WAIT0();
    __syncthreads();   // B2c
    for (int i = tid; i < 2048; i += NTHREADS) cp16(sb + (OFF_MWB0 << 2) + i * 16, g_w3img + i * 4);  // W3img
    CP_COMMIT();

    // q3: k 96..127 (scalar SWA, mma MWB1) + h2 epilogues
    if (is_s) {
        #pragma unroll 4
        for (int k = 96; k < 128; ++k) {
            float4 a0 = *(const float4*)(CTs + k*CS + r0);
            float4 a1 = *(const float4*)(CTs + k*CS + r0 + 4);
            ulonglong2 bq = *(const ulonglong2*)(SWA + (k-64)*128 + c0);
            float av[8] = {a0.x,a0.y,a0.z,a0.w,a1.x,a1.y,a1.z,a1.w};
            #pragma unroll
            for (int i = 0; i < 8; ++i) {
                u64 aa = bcast2(av[i]);
                fma2(acc2[i][0], aa, bq.x);
                fma2(acc2[i][1], aa, bq.y);
            }
        }
    } else {
        #pragma unroll 1
        for (int s = 0; s < 4; ++s) mma_step3(c, CTs, MW1, s, 12 + s, rowb, n8b, L, 16, 8);
    }
    __syncthreads();   // B2d: all h1 reads of CTs done before overwrite
    if (is_s) {
        #pragma unroll
        for (int jp = 0; jp < 2; ++jp) {
            int cc = c0 + 2*jp;
            float bias0 = B2s[cc], bias1 = B2s[cc+1];
            float v0[8], v1[8];
            #pragma unroll
            for (int i = 0; i < 8; ++i) {
                float x, y; unpack2(acc2[i][jp], x, y);
                v0[i] = fmaxf(x + bias0, 0.f);
                v1[i] = fmaxf(y + bias1, 0.f);
            }
            *(float4*)(CTs + cc*CS + r0)       = make_float4(v0[0],v0[1],v0[2],v0[3]);
            *(float4*)(CTs + cc*CS + r0 + 4)   = make_float4(v0[4],v0[5],v0[6],v0[7]);
            *(float4*)(CTs + (cc+1)*CS + r0)     = make_float4(v1[0],v1[1],v1[2],v1[3]);
            *(float4*)(CTs + (cc+1)*CS + r0 + 4) = make_float4(v1[4],v1[5],v1[6],v1[7]);
        }
    } else {
        int r = rowb + (L >> 2);
        #pragma unroll
        for (int i = 0; i < 8; ++i) {
            int cb = (n8b + i) * 8 + 2 * (L & 3);
            float bb0 = B2s[cb], bb1 = B2s[cb + 1];
            CTs[cb*CS + r]       = fmaxf(c[i][0] + bb0, 0.f);
            CTs[(cb+1)*CS + r]   = fmaxf(c[i][1] + bb1, 0.f);
            CTs[cb*CS + r + 8]     = fmaxf(c[i][2] + bb0, 0.f);
            CTs[(cb+1)*CS + r + 8] = fmaxf(c[i][3] + bb1, 0.f);
        }
    }
    CP_WAIT0();
    __syncthreads();   // B3 (W3img ready, SWB region dead -> aliases live)
    for (int i = tid; i < 1024; i += NTHREADS) cp16(sb + (OFF_MWB1 << 2) + i * 16, codebook + i * 4);  // CB
    CP_COMMIT();

    // ================= GEMM3 =================
    if (is_s) {
        // 256 threads: colpair cp=tid&15 -> cols 2cp,2cp+1 ; rowgrp=(tid>>4) -> 4 rows
        int cp = tid & 15;
        int c3 = 2 * cp;
        int rr0 = (tid >> 4) * 4;      // 0..60
        u64 acc3[4];
        #pragma unroll
        for (int i = 0; i < 4; ++i) acc3[i] = 0ULL;
        #pragma unroll 4
        for (int k = 0; k < 128; ++k) {
            float4 a0 = *(const float4*)(CTs + k*CS + rr0);
            u64 wp = *(const u64*)(W3S + k*32 + c3);
            float av[4] = {a0.x, a0.y, a0.z, a0.w};
            #pragma unroll
            for (int i = 0; i < 4; ++i) {
                u64 aa = bcast2(av[i]);
                fma2(acc3[i], aa, wp);
            }
        }
        float bias0 = BMLs[c3], bias1 = BMLs[c3 + 1];
        #pragma unroll
        for (int i = 0; i < 4; ++i) {
            float x, y; unpack2(acc3[i], x, y);
            MLB[(rr0 + i)*33 + c3]     = x + bias0;
            MLB[(rr0 + i)*33 + c3 + 1] = y + bias1;
        }
    } else {
        float c3f[8][4];
        #pragma unroll
        for (int i = 0; i < 2; ++i) { c3f[i][0] = c3f[i][1] = c3f[i][2] = c3f[i][3] = 0.f; }
        int n8b3 = (mw & 1) * 2;
        #pragma unroll 1
        for (int s = 0; s < 16; ++s) mma_step3(c3f, CTs, MW0, s, s, rowb, n8b3, L, 4, 2);
        int r = rowb + (L >> 2);
        #pragma unroll
        for (int i = 0; i < 2; ++i) {
            int cb = (n8b3 + i) * 8 + 2 * (L & 3);
            float bb0 = BMLs[cb], bb1 = BMLs[cb + 1];
            MLB[r*33 + cb]       = c3f[i][0] + bb0;
            MLB[r*33 + cb + 1]   = c3f[i][1] + bb1;
            MLB[(r+8)*33 + cb]     = c3f[i][2] + bb0;
            MLB[(r+8)*33 + cb + 1] = c3f[i][3] + bb1;
        }
    }
    CP_WAIT0();
    __syncthreads();   // B4 (CB ready, MLB complete)

    // ---- z-stage (all 128 rows) + mu/lv gmem writes ; CN compute ----
    if (tid < 256) {
        int row = tid >> 1;
        int d0  = (tid & 1) << 3;
        size_t g = (size_t)(row0 + row) * D_Z + d0;
        float4 e0 = *(const float4*)(eps + g);
        float4 e1 = *(const float4*)(eps + g + 4);
        float ev[8] = {e0.x,e0.y,e0.z,e0.w,e1.x,e1.y,e1.z,e1.w};
        float mu[8], lv[8], zv[8];
        #pragma unroll
        for (int q = 0; q < 8; ++q) {
            mu[q] = MLB[row*33 + d0 + q];
            lv[q] = MLB[row*33 + 16 + d0 + q];
            zv[q] = fmaf(ev[q], expf(0.5f * lv[q]), mu[q]);
        }
        *(float4*)(outMu + g)     = make_float4(mu[0],mu[1],mu[2],mu[3]);
        *(float4*)(outMu + g + 4) = make_float4(mu[4],mu[5],mu[6],mu[7]);
        *(float4*)(outLv + g)     = make_float4(lv[0],lv[1],lv[2],lv[3]);
        *(float4*)(outLv + g + 4) = make_float4(lv[4],lv[5],lv[6],lv[7]);
        *(float4*)(outZ + g)      = make_float4(zv[0],zv[1],zv[2],zv[3]);
        *(float4*)(outZ + g + 4)  = make_float4(zv[4],zv[5],zv[6],zv[7]);
        *(float4*)(ZS + row*20 + d0)     = make_float4(zv[0],zv[1],zv[2],zv[3]);
        *(float4*)(ZS + row*20 + d0 + 4) = make_float4(zv[4],zv[5],zv[6],zv[7]);
    } else {
        int cc = tid - 256;
        const float4* c4 = (const float4*)(CBs + cc * D_Z);
        float4 q0 = c4[0], q1 = c4[1], q2 = c4[2], q3 = c4[3];
        CNs[cc] = q0.x*q0.x + q0.y*q0.y + q0.z*q0.z + q0.w*q0.w
                + q1.x*q1.x + q1.y*q1.y + q1.z*q1.z + q1.w*q1.w
                + q2.x*q2.x + q2.y*q2.y + q2.z*q2.z + q2.w*q2.w
                + q3.x*q3.x + q3.y*q3.y + q3.z*q3.z + q3.w*q3.w;
    }
    __syncthreads();   // B5

    // ---- VQ dist: 4 quarters of 64 codes ----
    {
        int row = tid & 127;
        int qr  = tid >> 7;
        u64 zp[8];
        #pragma unroll
        for (int q = 0; q < 8; ++q) zp[q] = *(const u64*)(ZS + row*20 + 2*q);
        float best = 3.4e38f, sec = 3.4e38f;
        int bi = 0;
        int cbase = qr * 64;
        for (int cc = 0; cc < 64; ++cc) {
            const ulonglong2* q2p = (const ulonglong2*)(CBs + (cbase + cc) * D_Z);
            ulonglong2 qa = q2p[0], qb = q2p[1];
            u64 dp = 0ULL;
            fma2(dp, zp[0], qa.x); fma2(dp, zp[1], qa.y);
            fma2(dp, zp[2], qb.x); fma2(dp, zp[3], qb.y);
            ulonglong2 qc = q2p[2], qd = q2p[3];
            fma2(dp, zp[4], qc.x); fma2(dp, zp[5], qc.y);
            fma2(dp, zp[6], qd.x); fma2(dp, zp[7], qd.y);
            float dx, dy; unpack2(dp, dx, dy);
            float score = fmaf(-2.f, dx + dy, CNs[cbase + cc]);
            if (score < best) { sec = best; best = score; bi = cbase + cc; }
            else if (score < sec) { sec = score; }
        }
        REDs[tid] = best;
        SECs[tid] = sec;
        REDi[tid] = bi;
    }
    __syncthreads();   // B6

    float ss = 0.f;
    if (tid < 128) {
        int row = tid;
        float best = REDs[row], sec = SECs[row];
        int idx = REDi[row];
        #pragma unroll
        for (int q = 1; q < 4; ++q) {
            float b2 = REDs[q*128 + row];
            if (b2 < best) { sec = fminf(best, SECs[q*128 + row]); best = b2; idx = REDi[q*128 + row]; }
            else           { sec = fminf(sec, fminf(b2, SECs[q*128 + row])); }
        }
        size_t g = (size_t)(row0 + row) * D_Z;
        bool flag = (row >= 64) && ((sec - best) < MARGIN);
        if (flag) {
            int slot = atomicAdd(&g_fixcount, 1);
            g_fixlist[slot] = row0 + row;
            #pragma unroll
            for (int q4 = 0; q4 < 4; ++q4)
                *(float4*)(outZq + g + q4*4) = *(const float4*)(CBs + idx*D_Z + q4*4);
        } else {
            #pragma unroll
            for (int q4 = 0; q4 < 4; ++q4) {
                float4 qc = *(const float4*)(CBs + idx*D_Z + q4*4);
                float4 zz = *(const float4*)(ZS + row*20 + q4*4);
                float d0 = qc.x - zz.x, d1 = qc.y - zz.y, d2 = qc.z - zz.z, d3 = qc.w - zz.w;
                ss = fmaf(d0, d0, ss); ss = fmaf(d1, d1, ss);
                ss = fmaf(d2, d2, ss); ss = fmaf(d3, d3, ss);
                *(float4*)(outZq + g + q4*4) = qc;
            }
        }
    }
    __syncthreads();
    if (tid < 128) REDs[tid] = ss;
    __syncthreads();
    #pragma unroll
    for (int s = 64; s > 0; s >>= 1) {
        if (tid < s) REDs[tid] += REDs[tid + s];
        __syncthreads();
    }
    if (tid == 0) g_partial[tile] = REDs[0];
}

// ---- exact scalar recompute for flagged rows (validated in R8) ----
__global__ void fixup_kernel(const float* __restrict__ feats,
                             const float* __restrict__ W1,  const float* __restrict__ b1,
                             const float* __restrict__ W2,  const float* __restrict__ b2,
                             const float* __restrict__ Wmu, const float* __restrict__ bmu,
                             const float* __restrict__ Wlv, const float* __restrict__ blv,
                             const float* __restrict__ codebook, const float* __restrict__ eps,
                             float* __restrict__ outZ,  float* __restrict__ outMu,
                             float* __restrict__ outLv, float* __restrict__ outZq)
{
    int gw = (blockIdx.x * blockDim.x + threadIdx.x) >> 5;
    int L  = threadIdx.x & 31;
    int nw = (gridDim.x * blockDim.x) >> 5;
    int cnt = g_fixcount;
    for (int it = gw; it < cnt; it += nw) {
        int row = g_fixlist[it];
        const float* x = feats + (size_t)row * D_IN;
        float h1[4], h2[4];
        #pragma unroll
        for (int j = 0; j < 4; ++j) {
            int col = L + 32 * j;
            float acc = 0.f;
            for (int k = 0; k < 64; ++k) acc = fmaf(x[k], W1[k * 128 + col], acc);
            h1[j] = fmaxf(acc + b1[col], 0.f);
        }
        #pragma unroll
        for (int j = 0; j < 4; ++j) {
            int col = L + 32 * j;
            float acc = 0.f;
            for (int k = 0; k < 128; ++k) {
                float v = __shfl_sync(0xffffffffu, h1[k >> 5], k & 31);
                acc = fmaf(v, W2[k * 128 + col], acc);
            }
            h2[j] = fmaxf(acc + b2[col], 0.f);
        }
        float acc3 = 0.f;
        for (int k = 0; k < 128; ++k) {
            float v = __shfl_sync(0xffffffffu, h2[k >> 5], k & 31);
            float wv = (L < 16) ? Wmu[k * 16 + L] : Wlv[k * 16 + (L - 16)];
            acc3 = fmaf(v, wv, acc3);
        }
        float mulv = acc3 + ((L < 16) ? bmu[L] : blv[L - 16]);
        int d = L & 15;
        float muv = __shfl_sync(0xffffffffu, mulv, d);
        float lvv = __shfl_sync(0xffffffffu, mulv, d + 16);
        float z_d = fmaf(eps[(size_t)row * D_Z + d], expf(0.5f * lvv), muv);
        if (L < 16) { outMu[(size_t)row * D_Z + L] = mulv; outZ[(size_t)row * D_Z + L] = z_d; }
        else        { outLv[(size_t)row * D_Z + (L - 16)] = mulv; }
        float z[16];
        #pragma unroll
        for (int d2 = 0; d2 < 16; ++d2) z[d2] = __shfl_sync(0xffffffffu, z_d, d2);
        float best = 3.4e38f; int bi = 0;
        for (int t = 0; t < 8; ++t) {
            int cc = L * 8 + t;
            const float* q = codebook + cc * D_Z;
            float dx = 0.f, dy = 0.f;
            #pragma unroll
            for (int d2 = 0; d2 < 16; d2 += 2) {
                dx = fmaf(z[d2], q[d2], dx);
                dy = fmaf(z[d2 + 1], q[d2 + 1], dy);
            }
            float cn = q[0]*q[0] + q[1]*q[1] + q[2]*q[2] + q[3]*q[3]
                     + q[4]*q[4] + q[5]*q[5] + q[6]*q[6] + q[7]*q[7]
                     + q[8]*q[8] + q[9]*q[9] + q[10]*q[10] + q[11]*q[11]
                     + q[12]*q[12] + q[13]*q[13] + q[14]*q[14] + q[15]*q[15];
            float score = fmaf(-2.f, dx + dy, cn);
            if (score < best) { best = score; bi = cc; }
        }
        #pragma unroll
        for (int off = 16; off > 0; off >>= 1) {
            float so = __shfl_xor_sync(0xffffffffu, best, off);
            int   io = __shfl_xor_sync(0xffffffffu, bi, off);
            if (so < best || (so == best && io < bi)) { best = so; bi = io; }
        }
        float ssl = 0.f;
        if (L < 16) {
            float qv = codebook[bi * D_Z + L];
            outZq[(size_t)row * D_Z + L] = qv;
            float dd = qv - z_d;
            ssl = dd * dd;
        }
        #pragma unroll
        for (int off = 16; off > 0; off >>= 1) ssl += __shfl_xor_sync(0xffffffffu, ssl, off);
        if (L == 0) atomicAdd(&g_fixloss, ssl);
    }
}

__global__ void loss_kernel(float* __restrict__ out_loss)
{
    __shared__ float s[1024];
    float v = 0.f;
    for (int i = threadIdx.x; i < NTILES; i += 1024) v += g_partial[i];
    s[threadIdx.x] = v;
    __syncthreads();
    #pragma unroll
    for (int st = 512; st > 0; st >>= 1) {
        if (threadIdx.x < st) s[threadIdx.x] += s[threadIdx.x + st];
        __syncthreads();
    }
    if (threadIdx.x == 0) {
        float m = (s[0] + g_fixloss) / (float)((long long)N_ROWS * D_Z);
        out_loss[0] = 0.25f * (m + m);
    }
}

extern "C" void kernel_launch(void* const* d_in, const int* in_sizes, int n_in,
                              void* d_out, int out_size)
{
    const float* feats    = (const float*)d_in[0];
    const float* W1       = (const float*)d_in[1];
    const float* b1       = (const float*)d_in[2];
    const float* W2       = (const float*)d_in[3];
    const float* b2       = (const float*)d_in[4];
    const float* Wmu      = (const float*)d_in[5];
    const float* bmu      = (const float*)d_in[6];
    const float* Wlv      = (const float*)d_in[7];
    const float* blv      = (const float*)d_in[8];
    const float* codebook = (const float*)d_in[9];
    const float* eps      = (const float*)d_in[10];

    float* out = (float*)d_out;
    size_t sec = (size_t)N_ROWS * D_Z;

    setup_kernel<<<32, 256>>>(W1, W2, Wmu, Wlv);

    cudaFuncSetAttribute(enc_kernel, cudaFuncAttributeMaxDynamicSharedMemorySize, SMEM_BYTES);
    enc_kernel<<<NTILES, NTHREADS, SMEM_BYTES>>>(
        feats, W1, b1, W2, b2, Wmu, bmu, Wlv, blv, codebook, eps,
        out, out + sec, out + 2 * sec, out + 3 * sec);

    fixup_kernel<<<256, 256>>>(feats, W1, b1, W2, b2, Wmu, bmu, Wlv, blv,
                               codebook, eps,
                               out, out + sec, out + 2 * sec, out + 3 * sec);

    loss_kernel<<<1, 1024>>>(out + 4 * sec);
}

// round 15
// speedup vs baseline: 1.0015x; 1.0006x over previous
#include <cuda_runtime.h>
#include <math.h>
#include <stdint.h>

#define N_ROWS   524288
#define D_IN     64
#define H_DIM    128
#define D_Z      16
#define K_CODES  256
#define TILE_M   128
#define NTHREADS 512
#define NTILES   (N_ROWS / TILE_M)

#define CS   132      // CTs row stride (floats)
#define ASR  68       // ATs row stride
#define MARGIN 0.02f

// ---- smem layout (float offsets) ----
#define OFF_ATS  0            // 4352 ; alias W3S (4096) after G1
#define OFF_CTS  4352         // 16896 = 128 cols * 132
#define OFF_SWB  21248        // 16384 : A @ +0 (8192), B @ +8192
#define OFF_SWA  21248
#define OFF_SWBB 29440
// aliases into SWB region (dead after B3):
#define OFF_ZS   21248        // 2560
#define OFF_MLB  23808        // 4224 (128 rows * 33)
#define OFF_CN   28032        // 256
#define OFF_RED  28288        // 512
#define OFF_SEC  28800        // 512
#define OFF_REDI 29312        // 512
#define OFF_MWB0 37632        // 8192 (32KB)
#define OFF_MWB1 45824        // 8192 (32KB)
#define OFF_B1S  54016        // 128
#define OFF_B2S  54144        // 128
#define OFF_BML  54272        // 32
#define SMEM_FLOATS 54304
#define SMEM_BYTES  (SMEM_FLOATS * 4)   // 217216

typedef unsigned long long u64;

// mma weight images (hi/lo split, fragment-ordered)
__device__ __align__(16) float g_w1img[16384];   // 2 halves x 2048 float4
__device__ __align__(16) float g_w2img[32768];   // 4 quarters x 2048 float4
__device__ __align__(16) float g_w3img[8192];    // 2048 float4
__device__ float g_partial[NTILES];
__device__ int   g_fixcount;
__device__ float g_fixloss;
__device__ int   g_fixlist[N_ROWS];

// ---- helpers ----
__device__ __forceinline__ uint32_t smem_u32(const void* p) {
    uint32_t a;
    asm("{ .reg .u64 t; cvta.to.shared.u64 t, %1; cvt.u32.u64 %0, t; }" : "=r"(a) : "l"(p));
    return a;
}
__device__ __forceinline__ void split32(float v, uint32_t& h, uint32_t& l) {
    asm("cvt.rna.tf32.f32 %0, %1;" : "=r"(h) : "f"(v));
    float hf = __uint_as_float(h);
    asm("cvt.rna.tf32.f32 %0, %1;" : "=r"(l) : "f"(v - hf));
}
__device__ __forceinline__ void mma8(float* c, uint32_t a0, uint32_t a1, uint32_t a2, uint32_t a3,
                                     uint32_t b0, uint32_t b1) {
    asm volatile("mma.sync.aligned.m16n8k8.row.col.f32.tf32.tf32.f32 "
                 "{%0,%1,%2,%3},{%4,%5,%6,%7},{%8,%9},{%0,%1,%2,%3};"
                 : "+f"(c[0]), "+f"(c[1]), "+f"(c[2]), "+f"(c[3])
                 : "r"(a0), "r"(a1), "r"(a2), "r"(a3), "r"(b0), "r"(b1));
}
__device__ __forceinline__ void cp16(uint32_t dst, const void* src) {
    asm volatile("cp.async.cg.shared.global [%0], [%1], 16;" :: "r"(dst), "l"(src) : "memory");
}
#define CP_COMMIT() asm volatile("cp.async.commit_group;" ::: "memory")
#define CP_WAIT0()  asm volatile("cp.async.wait_group 0;" ::: "memory")

__device__ __forceinline__ u64 bcast2(float x) { u64 r; asm("mov.b64 %0, {%1, %1};" : "=l"(r) : "f"(x)); return r; }
__device__ __forceinline__ void unpack2(u64 v, float& x, float& y) { asm("mov.b64 {%0, %1}, %2;" : "=f"(x), "=f"(y) : "l"(v)); }
__device__ __forceinline__ void fma2(u64& d, u64 a, u64 b) { asm("fma.rn.f32x2 %0, %1, %2, %3;" : "=l"(d) : "l"(a), "l"(b), "l"(d)); }

// ---- setup: split weight images + reset fix state ----
__global__ void setup_kernel(const float* __restrict__ W1, const float* __restrict__ W2,
                             const float* __restrict__ Wmu, const float* __restrict__ Wlv)
{
    if (blockIdx.x == 0 && threadIdx.x == 0) { g_fixcount = 0; g_fixloss = 0.f; }
    int t = blockIdx.x * blockDim.x + threadIdx.x;
    int nt = gridDim.x * blockDim.x;
    // W1img: 2 halves (k 0-31, 32-63), each 2048 float4
    for (int e = t; e < 4096; e += nt) {
        int h = e >> 11, f = e & 2047;
        int sl = f >> 9, n8 = (f >> 5) & 15, L = f & 31;
        int k0 = h * 32 + sl * 8 + (L & 3), n = n8 * 8 + (L >> 2);
        uint32_t h0, l0, h1, l1;
        split32(W1[k0 * 128 + n], h0, l0);
        split32(W1[(k0 + 4) * 128 + n], h1, l1);
        ((float4*)g_w1img)[e] = make_float4(__uint_as_float(h0), __uint_as_float(h1),
                                            __uint_as_float(l0), __uint_as_float(l1));
    }
    // W2img: 4 quarters (k 0-31, 32-63, 64-95, 96-127)
    for (int e = t; e < 8192; e += nt) {
        int q = e >> 11, f = e & 2047;
        int sl = f >> 9, n8 = (f >> 5) & 15, L = f & 31;
        int k0 = q * 32 + sl * 8 + (L & 3), n = n8 * 8 + (L >> 2);
        uint32_t h0, l0, h1, l1;
        split32(W2[k0 * 128 + n], h0, l0);
        split32(W2[(k0 + 4) * 128 + n], h1, l1);
        ((float4*)g_w2img)[e] = make_float4(__uint_as_float(h0), __uint_as_float(h1),
                                            __uint_as_float(l0), __uint_as_float(l1));
    }
    // W3img: [Wmu|Wlv] 128k x 32n: 16 s x 4 n8
    for (int f = t; f < 2048; f += nt) {
        int s = f >> 7, n8 = (f >> 5) & 3, L = f & 31;
        int k0 = s * 8 + (L & 3), n = n8 * 8 + (L >> 2);
        float b0 = (n < 16) ? Wmu[k0 * 16 + n] : Wlv[k0 * 16 + n - 16];
        float b1 = (n < 16) ? Wmu[(k0 + 4) * 16 + n] : Wlv[(k0 + 4) * 16 + n - 16];
        uint32_t h0, l0, h1, l1;
        split32(b0, h0, l0); split32(b1, h1, l1);
        ((float4*)g_w3img)[f] = make_float4(__uint_as_float(h0), __uint_as_float(h1),
                                            __uint_as_float(l0), __uint_as_float(l1));
    }
}

// mma 3-term k-step, A from CTs (transposed [col][row])
__device__ __forceinline__ void mma_step3(float (*c)[4], const float* CTs, const uint4* img,
                                          int s_local, int kglob, int rowb, int n8base,
                                          int L, int NTIMG, int NT8)
{
    int k0 = kglob * 8 + (L & 3);
    int r  = rowb + (L >> 2);
    float a0v = CTs[k0 * CS + r];
    float a1v = CTs[k0 * CS + r + 8];
    float a2v = CTs[(k0 + 4) * CS + r];
    float a3v = CTs[(k0 + 4) * CS + r + 8];
    uint32_t ah0, al0, ah1, al1, ah2, al2, ah3, al3;
    split32(a0v, ah0, al0); split32(a1v, ah1, al1);
    split32(a2v, ah2, al2); split32(a3v, ah3, al3);
    #pragma unroll
    for (int i = 0; i < 8; ++i) {
        if (i >= NT8) break;
        uint4 B = img[(s_local * NTIMG + n8base + i) * 32 + L];
        mma8(c[i], ah0, ah1, ah2, ah3, B.x, B.y);
        mma8(c[i], ah0, ah1, ah2, ah3, B.z, B.w);
        mma8(c[i], al0, al1, al2, al3, B.x, B.y);
    }
}

// mma 3-term k-step, A from registers (GEMM1)
__device__ __forceinline__ void mma_g1step3(float (*c)[4], const float* aXs, const uint4* img,
                                            int s_local, int n8base, int L)
{
    uint32_t ah0, al0, ah1, al1, ah2, al2, ah3, al3;
    split32(aXs[0], ah0, al0); split32(aXs[1], ah1, al1);
    split32(aXs[2], ah2, al2); split32(aXs[3], ah3, al3);
    #pragma unroll
    for (int i = 0; i < 8; ++i) {
        uint4 B = img[(s_local * 16 + n8base + i) * 32 + L];
        mma8(c[i], ah0, ah1, ah2, ah3, B.x, B.y);
        mma8(c[i], ah0, ah1, ah2, ah3, B.z, B.w);
        mma8(c[i], al0, al1, al2, al3, B.x, B.y);
    }
}

__global__ __launch_bounds__(NTHREADS, 1)
void enc_kernel(const float* __restrict__ feats,
                const float* __restrict__ W1g,  const float* __restrict__ b1,
                const float* __restrict__ W2g,  const float* __restrict__ b2,
                const float* __restrict__ Wmu, const float* __restrict__ bmu,
                const float* __restrict__ Wlv, const float* __restrict__ blv,
                const float* __restrict__ codebook, const float* __restrict__ eps,
                float* __restrict__ outZ,  float* __restrict__ outMu,
                float* __restrict__ outLv, float* __restrict__ outZq)
{
    extern __shared__ float sm[];
    const uint32_t sb = smem_u32(sm);
    const int tid = threadIdx.x;
    const int w   = tid >> 5;
    const int L   = tid & 31;
    const int tile = blockIdx.x;
    const int row0 = tile * TILE_M;

    float* ATs  = sm + OFF_ATS;
    float* W3S  = sm + OFF_ATS;      // alias after G1
    float* CTs  = sm + OFF_CTS;
    float* SWA  = sm + OFF_SWA;
    float* SWBB = sm + OFF_SWBB;
    float* ZS   = sm + OFF_ZS;
    float* MLB  = sm + OFF_MLB;
    float* CNs  = sm + OFF_CN;
    float* REDs = sm + OFF_RED;
    float* SECs = sm + OFF_SEC;
    int*   REDi = (int*)(sm + OFF_REDI);
    float* B1s  = sm + OFF_B1S;
    float* B2s  = sm + OFF_B2S;
    float* BMLs = sm + OFF_BML;
    const uint4* MW0 = (const uint4*)(sm + OFF_MWB0);
    const uint4* MW1 = (const uint4*)(sm + OFF_MWB1);
    const float* CBs = sm + OFF_MWB1;   // codebook lands in MWB1 at the end

    const bool is_s = (w < 8);
    const int  mw   = w - 8;                       // mma warp id 0..7
    const int  rowb = 64 + ((mw >> 1) & 3) * 16;   // mma rows
    const int  n8b  = (mw & 1) * 8;                // mma col half

    // scalar mapping
    const int stx = tid & 31;
    const int sty = tid >> 5;        // 0..7 for scalar threads
    const int r0  = sty * 8;
    const int c0  = stx * 4;

    // ---- preload copies ----
    for (int i = tid; i < 2048; i += NTHREADS) cp16(sb + (OFF_SWA << 2) + i * 16, W1g + i * 4);
    for (int i = tid; i < 2048; i += NTHREADS) cp16(sb + (OFF_SWBB << 2) + i * 16, W2g + i * 4);
    for (int i = tid; i < 2048; i += NTHREADS) cp16(sb + (OFF_MWB0 << 2) + i * 16, g_w1img + i * 4);
    for (int i = tid; i < 2048; i += NTHREADS) cp16(sb + (OFF_MWB1 << 2) + i * 16, g_w1img + 8192 + i * 4);
    CP_COMMIT();

    // X transpose (rows 0..63) for scalar half
    {
        const float4* Xg = (const float4*)(feats + (size_t)row0 * D_IN);
        #pragma unroll
        for (int it = 0; it < 2; ++it) {
            int i = tid + it * NTHREADS;   // 0..1023
            float4 v = Xg[i];
            int r  = i >> 4;
            int k0 = (i & 15) << 2;
            ATs[(k0+0)*ASR + r] = v.x;
            ATs[(k0+1)*ASR + r] = v.y;
            ATs[(k0+2)*ASR + r] = v.z;
            ATs[(k0+3)*ASR + r] = v.w;
        }
    }
    // mma X fragments (rows 64..127) from gmem
    float aX[8][4];
    if (!is_s) {
        const float* fb = feats + (size_t)(row0 + rowb + (L >> 2)) * D_IN + (L & 3);
        #pragma unroll
        for (int s = 0; s < 8; ++s) {
            aX[s][0] = fb[s * 8];
            aX[s][1] = fb[512 + s * 8];
            aX[s][2] = fb[s * 8 + 4];
            aX[s][3] = fb[512 + s * 8 + 4];
        }
    }
    if (tid < 128) { B1s[tid] = b1[tid]; B2s[tid] = b2[tid]; }
    if (tid >= 128 && tid < 160) { int q = tid - 128; BMLs[q] = (q < 16) ? bmu[q] : blv[q - 16]; }

    CP_WAIT0();
    __syncthreads();   // B0

    // scalar accumulators
    u64 acc2[8][2];
    #pragma unroll
    for (int i = 0; i < 8; ++i) { acc2[i][0] = 0ULL; acc2[i][1] = 0ULL; }
    // mma accumulators
    float c[8][4];
    #pragma unroll
    for (int i = 0; i < 8; ++i) { c[i][0] = c[i][1] = c[i][2] = c[i][3] = 0.f; }

    // ================= GEMM1 part a (k 0..31) =================
    if (is_s) {
        #pragma unroll 4
        for (int k = 0; k < 32; ++k) {
            float4 a0 = *(const float4*)(ATs + k*ASR + r0);
            float4 a1 = *(const float4*)(ATs + k*ASR + r0 + 4);
            ulonglong2 bq = *(const ulonglong2*)(SWA + k*128 + c0);
            float av[8] = {a0.x,a0.y,a0.z,a0.w,a1.x,a1.y,a1.z,a1.w};
            #pragma unroll
            for (int i = 0; i < 8; ++i) {
                u64 aa = bcast2(av[i]);
                fma2(acc2[i][0], aa, bq.x);
                fma2(acc2[i][1], aa, bq.y);
            }
        }
    } else {
        #pragma unroll 1
        for (int s = 0; s < 4; ++s) mma_g1step3(c, aX[s], MW0, s, n8b, L);
    }
    __syncthreads();   // B1a (MWB0 free)
    for (int i = tid; i < 2048; i += NTHREADS) cp16(sb + (OFF_MWB0 << 2) + i * 16, g_w2img + i * 4);  // W2q0
    CP_COMMIT();

    // ================= GEMM1 part b (k 32..63) =================
    if (is_s) {
        #pragma unroll 4
        for (int k = 32; k < 64; ++k) {
            float4 a0 = *(const float4*)(ATs + k*ASR + r0);
            float4 a1 = *(const float4*)(ATs + k*ASR + r0 + 4);
            ulonglong2 bq = *(const ulonglong2*)(SWA + k*128 + c0);
            float av[8] = {a0.x,a0.y,a0.z,a0.w,a1.x,a1.y,a1.z,a1.w};
            #pragma unroll
            for (int i = 0; i < 8; ++i) {
                u64 aa = bcast2(av[i]);
                fma2(acc2[i][0], aa, bq.x);
                fma2(acc2[i][1], aa, bq.y);
            }
        }
        // scalar h1 epilogue -> CTs
        #pragma unroll
        for (int jp = 0; jp < 2; ++jp) {
            int cc = c0 + 2*jp;
            float bias0 = B1s[cc], bias1 = B1s[cc+1];
            float v0[8], v1[8];
            #pragma unroll
            for (int i = 0; i < 8; ++i) {
                float x, y; unpack2(acc2[i][jp], x, y);
                v0[i] = fmaxf(x + bias0, 0.f);
                v1[i] = fmaxf(y + bias1, 0.f);
            }
            *(float4*)(CTs + cc*CS + r0)       = make_float4(v0[0],v0[1],v0[2],v0[3]);
            *(float4*)(CTs + cc*CS + r0 + 4)   = make_float4(v0[4],v0[5],v0[6],v0[7]);
            *(float4*)(CTs + (cc+1)*CS + r0)     = make_float4(v1[0],v1[1],v1[2],v1[3]);
            *(float4*)(CTs + (cc+1)*CS + r0 + 4) = make_float4(v1[4],v1[5],v1[6],v1[7]);
        }
    } else {
        #pragma unroll 1
        for (int s = 0; s < 4; ++s) mma_g1step3(c, aX[4 + s], MW1, s, n8b, L);
        // mma h1 epilogue -> CTs (transposed scalar stores)
        int r = rowb + (L >> 2);
        #pragma unroll
        for (int i = 0; i < 8; ++i) {
            int cb = (n8b + i) * 8 + 2 * (L & 3);
            float bb0 = B1s[cb], bb1 = B1s[cb + 1];
            CTs[cb*CS + r]       = fmaxf(c[i][0] + bb0, 0.f);
            CTs[(cb+1)*CS + r]   = fmaxf(c[i][1] + bb1, 0.f);
            CTs[cb*CS + r + 8]     = fmaxf(c[i][2] + bb0, 0.f);
            CTs[(cb+1)*CS + r + 8] = fmaxf(c[i][3] + bb1, 0.f);
        }
    }
    CP_WAIT0();
    __syncthreads();   // B1b (ATs free, MWB1 free, W2q0 ready)
    for (int i = tid; i < 2048; i += NTHREADS) cp16(sb + (OFF_MWB1 << 2) + i * 16, g_w2img + 8192 + i * 4);  // W2q1
    for (int i = tid; i < 2048; i += NTHREADS) cp16(sb + (OFF_SWA << 2) + i * 16, W2g + 8192 + i * 4);       // W2h1 fp32
    for (int i = tid; i < 1024; i += NTHREADS) {  // scalar W3 pack [k][32]
        int k = i >> 3, cc = i & 7;
        uint32_t dst = sb + (OFF_ATS << 2) + (k * 32 + ((cc & 3) << 2) + ((cc >> 2) << 4)) * 4;
        const float* src = (cc < 4) ? (Wmu + k * 16 + ((cc & 3) << 2))
                                    : (Wlv + k * 16 + ((cc & 3) << 2));
        cp16(dst, src);
    }
    CP_COMMIT();

    // reset accumulators for GEMM2
    #pragma unroll
    for (int i = 0; i < 8; ++i) { acc2[i][0] = 0ULL; acc2[i][1] = 0ULL; }
    #pragma unroll
    for (int i = 0; i < 8; ++i) { c[i][0] = c[i][1] = c[i][2] = c[i][3] = 0.f; }

    // ================= GEMM2 in 4 k-quarters =================
    // q0: k 0..31 (scalar SWBB, mma MWB0)
    if (is_s) {
        #pragma unroll 4
        for (int k = 0; k < 32; ++k) {
            float4 a0 = *(const float4*)(CTs + k*CS + r0);
            float4 a1 = *(const float4*)(CTs + k*CS + r0 + 4);
            ulonglong2 bq = *(const ulonglong2*)(SWBB + k*128 + c0);
            float av[8] = {a0.x,a0.y,a0.z,a0.w,a1.x,a1.y,a1.z,a1.w};
            #pragma unroll
            for (int i = 0; i < 8; ++i) {
                u64 aa = bcast2(av[i]);
                fma2(acc2[i][0], aa, bq.x);
                fma2(acc2[i][1], aa, bq.y);
            }
        }
    } else {
        #pragma unroll 1
        for (int s = 0; s < 4; ++s) mma_step3(c, CTs, MW0, s, s, rowb, n8b, L, 16, 8);
    }
    CP_WAIT0();
    __syncthreads();   // B2a
    for (int i = tid; i < 2048; i += NTHREADS) cp16(sb + (OFF_MWB0 << 2) + i * 16, g_w2img + 16384 + i * 4);  // W2q2
    CP_COMMIT();

    // q1: k 32..63 (scalar SWBB, mma MWB1)
    if (is_s) {
        #pragma unroll 4
        for (int k = 32; k < 64; ++k) {
            float4 a0 = *(const float4*)(CTs + k*CS + r0);
            float4 a1 = *(const float4*)(CTs + k*CS + r0 + 4);
            ulonglong2 bq = *(const ulonglong2*)(SWBB + k*128 + c0);
            float av[8] = {a0.x,a0.y,a0.z,a0.w,a1.x,a1.y,a1.z,a1.w};
            #pragma unroll
            for (int i = 0; i < 8; ++i) {
                u64 aa = bcast2(av[i]);
                fma2(acc2[i][0], aa, bq.x);
                fma2(acc2[i][1], aa, bq.y);
            }
        }
    } else {
        #pragma unroll 1
        for (int s = 0; s < 4; ++s) mma_step3(c, CTs, MW1, s, 4 + s, rowb, n8b, L, 16, 8);
    }
    CP_WAIT0();
    __syncthreads();   // B2b
    for (int i = tid; i < 2048; i += NTHREADS) cp16(sb + (OFF_MWB1 << 2) + i * 16, g_w2img + 24576 + i * 4);  // W2q3
    CP_COMMIT();

    // q2: k 64..95 (scalar SWA, mma MWB0)
    if (is_s) {
        #pragma unroll 4
        for (int k = 64; k < 96; ++k) {
            float4 a0 = *(const float4*)(CTs + k*CS + r0);
            float4 a1 = *(const float4*)(CTs + k*CS + r0 + 4);
            ulonglong2 bq = *(const ulonglong2*)(SWA + (k-64)*128 + c0);
            float av[8] = {a0.x,a0.y,a0.z,a0.w,a1.x,a1.y,a1.z,a1.w};
            #pragma unroll
            for (int i = 0; i < 8; ++i) {
                u64 aa = bcast2(av[i]);
                fma2(acc2[i][0], aa, bq.x);
                fma2(acc2[i][1], aa, bq.y);
            }
        }
    } else {
        #pragma unroll 1
        for (int s = 0; s < 4; ++s) mma_step3(c, CTs, MW0, s, 8 + s, rowb, n8b, L, 16, 8);
    }
    CP_WAIT0();
    __syncthreads();   // B2c
    for (int i = tid; i < 2048; i += NTHREADS) cp16(sb + (OFF_MWB0 << 2) + i * 16, g_w3img + i * 4);  // W3img
    CP_COMMIT();

    // q3: k 96..127 (scalar SWA, mma MWB1) + h2 epilogues
    if (is_s) {
        #pragma unroll 4
        for (int k = 96; k < 128; ++k) {
            float4 a0 = *(const float4*)(CTs + k*CS + r0);
            float4 a1 = *(const float4*)(CTs + k*CS + r0 + 4);
            ulonglong2 bq = *(const ulonglong2*)(SWA + (k-64)*128 + c0);
            float av[8] = {a0.x,a0.y,a0.z,a0.w,a1.x,a1.y,a1.z,a1.w};
            #pragma unroll
            for (int i = 0; i < 8; ++i) {
                u64 aa = bcast2(av[i]);
                fma2(acc2[i][0], aa, bq.x);
                fma2(acc2[i][1], aa, bq.y);
            }
        }
    } else {
        #pragma unroll 1
        for (int s = 0; s < 4; ++s) mma_step3(c, CTs, MW1, s, 12 + s, rowb, n8b, L, 16, 8);
    }
    __syncthreads();   // B2d: all h1 reads of CTs done before overwrite
    if (is_s) {
        #pragma unroll
        for (int jp = 0; jp < 2; ++jp) {
            int cc = c0 + 2*jp;
            float bias0 = B2s[cc], bias1 = B2s[cc+1];
            float v0[8], v1[8];
            #pragma unroll
            for (int i = 0; i < 8; ++i) {
                float x, y; unpack2(acc2[i][jp], x, y);
                v0[i] = fmaxf(x + bias0, 0.f);
                v1[i] = fmaxf(y + bias1, 0.f);
            }
            *(float4*)(CTs + cc*CS + r0)       = make_float4(v0[0],v0[1],v0[2],v0[3]);
            *(float4*)(CTs + cc*CS + r0 + 4)   = make_float4(v0[4],v0[5],v0[6],v0[7]);
            *(float4*)(CTs + (cc+1)*CS + r0)     = make_float4(v1[0],v1[1],v1[2],v1[3]);
            *(float4*)(CTs + (cc+1)*CS + r0 + 4) = make_float4(v1[4],v1[5],v1[6],v1[7]);
        }
    } else {
        int r = rowb + (L >> 2);
        #pragma unroll
        for (int i = 0; i < 8; ++i) {
            int cb = (n8b + i) * 8 + 2 * (L & 3);
            float bb0 = B2s[cb], bb1 = B2s[cb + 1];
            CTs[cb*CS + r]       = fmaxf(c[i][0] + bb0, 0.f);
            CTs[(cb+1)*CS + r]   = fmaxf(c[i][1] + bb1, 0.f);
            CTs[cb*CS + r + 8]     = fmaxf(c[i][2] + bb0, 0.f);
            CTs[(cb+1)*CS + r + 8] = fmaxf(c[i][3] + bb1, 0.f);
        }
    }
    CP_WAIT0();
    __syncthreads();   // B3 (W3img ready, SWB region dead -> aliases live)
    for (int i = tid; i < 1024; i += NTHREADS) cp16(sb + (OFF_MWB1 << 2) + i * 16, codebook + i * 4);  // CB
    CP_COMMIT();

    // ================= GEMM3 =================
    if (is_s) {
        // 256 threads: colpair cp=tid&15 -> cols 2cp,2cp+1 ; rowgrp=(tid>>4) -> 4 rows
        int cp = tid & 15;
        int c3 = 2 * cp;
        int rr0 = (tid >> 4) * 4;      // 0..60
        u64 acc3[4];
        #pragma unroll
        for (int i = 0; i < 4; ++i) acc3[i] = 0ULL;
        #pragma unroll 4
        for (int k = 0; k < 128; ++k) {
            float4 a0 = *(const float4*)(CTs + k*CS + rr0);
            u64 wp = *(const u64*)(W3S + k*32 + c3);
            float av[4] = {a0.x, a0.y, a0.z, a0.w};
            #pragma unroll
            for (int i = 0; i < 4; ++i) {
                u64 aa = bcast2(av[i]);
                fma2(acc3[i], aa, wp);
            }
        }
        float bias0 = BMLs[c3], bias1 = BMLs[c3 + 1];
        #pragma unroll
        for (int i = 0; i < 4; ++i) {
            float x, y; unpack2(acc3[i], x, y);
            MLB[(rr0 + i)*33 + c3]     = x + bias0;
            MLB[(rr0 + i)*33 + c3 + 1] = y + bias1;
        }
    } else {
        float c3f[8][4];
        #pragma unroll
        for (int i = 0; i < 2; ++i) { c3f[i][0] = c3f[i][1] = c3f[i][2] = c3f[i][3] = 0.f; }
        int n8b3 = (mw & 1) * 2;
        #pragma unroll 1
        for (int s = 0; s < 16; ++s) mma_step3(c3f, CTs, MW0, s, s, rowb, n8b3, L, 4, 2);
        int r = rowb + (L >> 2);
        #pragma unroll
        for (int i = 0; i < 2; ++i) {
            int cb = (n8b3 + i) * 8 + 2 * (L & 3);
            float bb0 = BMLs[cb], bb1 = BMLs[cb + 1];
            MLB[r*33 + cb]       = c3f[i][0] + bb0;
            MLB[r*33 + cb + 1]   = c3f[i][1] + bb1;
            MLB[(r+8)*33 + cb]     = c3f[i][2] + bb0;
            MLB[(r+8)*33 + cb + 1] = c3f[i][3] + bb1;
        }
    }
    CP_WAIT0();
    __syncthreads();   // B4 (CB ready, MLB complete)

    // ---- z-stage (all 128 rows) + mu/lv gmem writes ; CN compute ----
    if (tid < 256) {
        int row = tid >> 1;
        int d0  = (tid & 1) << 3;
        size_t g = (size_t)(row0 + row) * D_Z + d0;
        float4 e0 = *(const float4*)(eps + g);
        float4 e1 = *(const float4*)(eps + g + 4);
        float ev[8] = {e0.x,e0.y,e0.z,e0.w,e1.x,e1.y,e1.z,e1.w};
        float mu[8], lv[8], zv[8];
        #pragma unroll
        for (int q = 0; q < 8; ++q) {
            mu[q] = MLB[row*33 + d0 + q];
            lv[q] = MLB[row*33 + 16 + d0 + q];
            zv[q] = fmaf(ev[q], expf(0.5f * lv[q]), mu[q]);
        }
        *(float4*)(outMu + g)     = make_float4(mu[0],mu[1],mu[2],mu[3]);
        *(float4*)(outMu + g + 4) = make_float4(mu[4],mu[5],mu[6],mu[7]);
        *(float4*)(outLv + g)     = make_float4(lv[0],lv[1],lv[2],lv[3]);
        *(float4*)(outLv + g + 4) = make_float4(lv[4],lv[5],lv[6],lv[7]);
        *(float4*)(outZ + g)      = make_float4(zv[0],zv[1],zv[2],zv[3]);
        *(float4*)(outZ + g + 4)  = make_float4(zv[4],zv[5],zv[6],zv[7]);
        *(float4*)(ZS + row*20 + d0)     = make_float4(zv[0],zv[1],zv[2],zv[3]);
        *(float4*)(ZS + row*20 + d0 + 4) = make_float4(zv[4],zv[5],zv[6],zv[7]);
    } else {
        int cc = tid - 256;
        const float4* c4 = (const float4*)(CBs + cc * D_Z);
        float4 q0 = c4[0], q1 = c4[1], q2 = c4[2], q3 = c4[3];
        CNs[cc] = q0.x*q0.x + q0.y*q0.y + q0.z*q0.z + q0.w*q0.w
                + q1.x*q1.x + q1.y*q1.y + q1.z*q1.z + q1.w*q1.w
                + q2.x*q2.x + q2.y*q2.y + q2.z*q2.z + q2.w*q2.w
                + q3.x*q3.x + q3.y*q3.y + q3.z*q3.z + q3.w*q3.w;
    }
    __syncthreads();   // B5

    // ---- VQ dist: 4 quarters of 64 codes ----
    {
        int row = tid & 127;
        int qr  = tid >> 7;
        u64 zp[8];
        #pragma unroll
        for (int q = 0; q < 8; ++q) zp[q] = *(const u64*)(ZS + row*20 + 2*q);
        float best = 3.4e38f, sec = 3.4e38f;
        int bi = 0;
        int cbase = qr * 64;
        for (int cc = 0; cc < 64; ++cc) {
            const ulonglong2* q2p = (const ulonglong2*)(CBs + (cbase + cc) * D_Z);
            ulonglong2 qa = q2p[0], qb = q2p[1];
            u64 dp = 0ULL;
            fma2(dp, zp[0], qa.x); fma2(dp, zp[1], qa.y);
            fma2(dp, zp[2], qb.x); fma2(dp, zp[3], qb.y);
            ulonglong2 qc = q2p[2], qd = q2p[3];
            fma2(dp, zp[4], qc.x); fma2(dp, zp[5], qc.y);
            fma2(dp, zp[6], qd.x); fma2(dp, zp[7], qd.y);
            float dx, dy; unpack2(dp, dx, dy);
            float score = fmaf(-2.f, dx + dy, CNs[cbase + cc]);
            if (score < best) { sec = best; best = score; bi = cbase + cc; }
            else if (score < sec) { sec = score; }
        }
        REDs[tid] = best;
        SECs[tid] = sec;
        REDi[tid] = bi;
    }
    __syncthreads();   // B6

    float ss = 0.f;
    if (tid < 128) {
        int row = tid;
        float best = REDs[row], sec = SECs[row];
        int idx = REDi[row];
        #pragma unroll
        for (int q = 1; q < 4; ++q) {
            float b2 = REDs[q*128 + row];
            if (b2 < best) { sec = fminf(best, SECs[q*128 + row]); best = b2; idx = REDi[q*128 + row]; }
            else           { sec = fminf(sec, fminf(b2, SECs[q*128 + row])); }
        }
        size_t g = (size_t)(row0 + row) * D_Z;
        bool flag = (row >= 64) && ((sec - best) < MARGIN);
        if (flag) {
            int slot = atomicAdd(&g_fixcount, 1);
            g_fixlist[slot] = row0 + row;
            #pragma unroll
            for (int q4 = 0; q4 < 4; ++q4)
                *(float4*)(outZq + g + q4*4) = *(const float4*)(CBs + idx*D_Z + q4*4);
        } else {
            #pragma unroll
            for (int q4 = 0; q4 < 4; ++q4) {
                float4 qc = *(const float4*)(CBs + idx*D_Z + q4*4);
                float4 zz = *(const float4*)(ZS + row*20 + q4*4);
                float d0 = qc.x - zz.x, d1 = qc.y - zz.y, d2 = qc.z - zz.z, d3 = qc.w - zz.w;
                ss = fmaf(d0, d0, ss); ss = fmaf(d1, d1, ss);
                ss = fmaf(d2, d2, ss); ss = fmaf(d3, d3, ss);
                *(float4*)(outZq + g + q4*4) = qc;
            }
        }
    }
    __syncthreads();
    if (tid < 128) REDs[tid] = ss;
    __syncthreads();
    #pragma unroll
    for (int s = 64; s > 0; s >>= 1) {
        if (tid < s) REDs[tid] += REDs[tid + s];
        __syncthreads();
    }
    if (tid == 0) g_partial[tile] = REDs[0];
}

// ---- exact scalar recompute for flagged rows (validated in R8) ----
__global__ void fixup_kernel(const float* __restrict__ feats,
                             const float* __restrict__ W1,  const float* __restrict__ b1,
                             const float* __restrict__ W2,  const float* __restrict__ b2,
                             const float* __restrict__ Wmu, const float* __restrict__ bmu,
                             const float* __restrict__ Wlv, const float* __restrict__ blv,
                             const float* __restrict__ codebook, const float* __restrict__ eps,
                             float* __restrict__ outZ,  float* __restrict__ outMu,
                             float* __restrict__ outLv, float* __restrict__ outZq)
{
    int gw = (blockIdx.x * blockDim.x + threadIdx.x) >> 5;
    int L  = threadIdx.x & 31;
    int nw = (gridDim.x * blockDim.x) >> 5;
    int cnt = g_fixcount;
    for (int it = gw; it < cnt; it += nw) {
        int row = g_fixlist[it];
        const float* x = feats + (size_t)row * D_IN;
        float h1[4], h2[4];
        #pragma unroll
        for (int j = 0; j < 4; ++j) {
            int col = L + 32 * j;
            float acc = 0.f;
            for (int k = 0; k < 64; ++k) acc = fmaf(x[k], W1[k * 128 + col], acc);
            h1[j] = fmaxf(acc + b1[col], 0.f);
        }
        #pragma unroll
        for (int j = 0; j < 4; ++j) {
            int col = L + 32 * j;
            float acc = 0.f;
            for (int k = 0; k < 128; ++k) {
                float v = __shfl_sync(0xffffffffu, h1[k >> 5], k & 31);
                acc = fmaf(v, W2[k * 128 + col], acc);
            }
            h2[j] = fmaxf(acc + b2[col], 0.f);
        }
        float acc3 = 0.f;
        for (int k = 0; k < 128; ++k) {
            float v = __shfl_sync(0xffffffffu, h2[k >> 5], k & 31);
            float wv = (L < 16) ? Wmu[k * 16 + L] : Wlv[k * 16 + (L - 16)];
            acc3 = fmaf(v, wv, acc3);
        }
        float mulv = acc3 + ((L < 16) ? bmu[L] : blv[L - 16]);
        int d = L & 15;
        float muv = __shfl_sync(0xffffffffu, mulv, d);
        float lvv = __shfl_sync(0xffffffffu, mulv, d + 16);
        float z_d = fmaf(eps[(size_t)row * D_Z + d], expf(0.5f * lvv), muv);
        if (L < 16) { outMu[(size_t)row * D_Z + L] = mulv; outZ[(size_t)row * D_Z + L] = z_d; }
        else        { outLv[(size_t)row * D_Z + (L - 16)] = mulv; }
        float z[16];
        #pragma unroll
        for (int d2 = 0; d2 < 16; ++d2) z[d2] = __shfl_sync(0xffffffffu, z_d, d2);
        float best = 3.4e38f; int bi = 0;
        for (int t = 0; t < 8; ++t) {
            int cc = L * 8 + t;
            const float* q = codebook + cc * D_Z;
            float dx = 0.f, dy = 0.f;
            #pragma unroll
            for (int d2 = 0; d2 < 16; d2 += 2) {
                dx = fmaf(z[d2], q[d2], dx);
                dy = fmaf(z[d2 + 1], q[d2 + 1], dy);
            }
            float cn = q[0]*q[0] + q[1]*q[1] + q[2]*q[2] + q[3]*q[3]
                     + q[4]*q[4] + q[5]*q[5] + q[6]*q[6] + q[7]*q[7]
                     + q[8]*q[8] + q[9]*q[9] + q[10]*q[10] + q[11]*q[11]
                     + q[12]*q[12] + q[13]*q[13] + q[14]*q[14] + q[15]*q[15];
            float score = fmaf(-2.f, dx + dy, cn);
            if (score < best) { best = score; bi = cc; }
        }
        #pragma unroll
        for (int off = 16; off > 0; off >>= 1) {
            float so = __shfl_xor_sync(0xffffffffu, best, off);
            int   io = __shfl_xor_sync(0xffffffffu, bi, off);
            if (so < best || (so == best && io < bi)) { best = so; bi = io; }
        }
        float ssl = 0.f;
        if (L < 16) {
            float qv = codebook[bi * D_Z + L];
            outZq[(size_t)row * D_Z + L] = qv;
            float dd = qv - z_d;
            ssl = dd * dd;
        }
        #pragma unroll
        for (int off = 16; off > 0; off >>= 1) ssl += __shfl_xor_sync(0xffffffffu, ssl, off);
        if (L == 0) atomicAdd(&g_fixloss, ssl);
    }
}

__global__ void loss_kernel(float* __restrict__ out_loss)
{
    __shared__ float s[1024];
    float v = 0.f;
    for (int i = threadIdx.x; i < NTILES; i += 1024) v += g_partial[i];
    s[threadIdx.x] = v;
    __syncthreads();
    #pragma unroll
    for (int st = 512; st > 0; st >>= 1) {
        if (threadIdx.x < st) s[threadIdx.x] += s[threadIdx.x + st];
        __syncthreads();
    }
    if (threadIdx.x == 0) {
        float m = (s[0] + g_fixloss) / (float)((long long)N_ROWS * D_Z);
        out_loss[0] = 0.25f * (m + m);
    }
}

extern "C" void kernel_launch(void* const* d_in, const int* in_sizes, int n_in,
                              void* d_out, int out_size)
{
    const float* feats    = (const float*)d_in[0];
    const float* W1       = (const float*)d_in[1];
    const float* b1       = (const float*)d_in[2];
    const float* W2       = (const float*)d_in[3];
    const float* b2       = (const float*)d_in[4];
    const float* Wmu      = (const float*)d_in[5];
    const float* bmu      = (const float*)d_in[6];
    const float* Wlv      = (const float*)d_in[7];
    const float* blv      = (const float*)d_in[8];
    const float* codebook = (const float*)d_in[9];
    const float* eps      = (const float*)d_in[10];

    float* out = (float*)d_out;
    size_t sec = (size_t)N_ROWS * D_Z;

    setup_kernel<<<32, 256>>>(W1, W2, Wmu, Wlv);

    cudaFuncSetAttribute(enc_kernel, cudaFuncAttributeMaxDynamicSharedMemorySize, SMEM_BYTES);
    enc_kernel<<<NTILES, NTHREADS, SMEM_BYTES>>>(
        feats, W1, b1, W2, b2, Wmu, bmu, Wlv, blv, codebook, eps,
        out, out + sec, out + 2 * sec, out + 3 * sec);

    fixup_kernel<<<256, 256>>>(feats, W1, b1, W2, b2, Wmu, bmu, Wlv, blv,
                               codebook, eps,
                               out, out + sec, out + 2 * sec, out + 3 * sec);

    loss_kernel<<<1, 1024>>>(out + 4 * sec);
}